// round 1
// baseline (speedup 1.0000x reference)
#include <cuda_runtime.h>
#include <math.h>

#define BB 32
#define TT 512
#define DIN 1824
#define HH 512
#define G4 2048
#define KK 30
#define TSTART 28
#define TSTOP 29
#define NEGV (-10000.0f)
#define MTOT (TT*BB)            /* 16384 */
#define NBLK 128

// ------------------------- device scratch -------------------------
__device__ float g_xw[2][(size_t)MTOT*G4];      // [dir][m][4H], m = t*B+b
__device__ float g_hs[2][(size_t)MTOT*HH];      // hf/hb, [t][b][d]
__device__ float g_hbuf[2][2][BB*HH];           // [parity][dir][b][d]
__device__ float g_feats[(size_t)BB*TT*KK];     // [b][t][k]
__device__ unsigned g_barcnt = 0;
__device__ volatile unsigned g_bargen = 0;

// ------------------------- input projection GEMM -------------------------
#define BM 128
#define BN 128
#define BKK 16

__global__ __launch_bounds__(256) void k_gemm(const float* __restrict__ embed,
                                              const int* __restrict__ ids,
                                              const float* __restrict__ W,
                                              const float* __restrict__ bias,
                                              int dir)
{
    __shared__ float As[BKK][BM];
    __shared__ float Bs[BKK][BN];
    __shared__ int rid[BM];
    float* out = g_xw[dir];
    int tid = threadIdx.x;
    int m0 = blockIdx.y * BM;
    int n0 = blockIdx.x * BN;
    if (tid < BM) {
        int m = m0 + tid;
        rid[tid] = ids[(m & 31) * TT + (m >> 5)];   // ids[b][t], b=m%32, t=m/32
    }
    __syncthreads();
    int tx = tid & 15, ty = tid >> 4;
    float acc[8][8];
#pragma unroll
    for (int i = 0; i < 8; i++)
#pragma unroll
        for (int j = 0; j < 8; j++) acc[i][j] = 0.f;

    for (int k0 = 0; k0 < DIN; k0 += BKK) {
#pragma unroll
        for (int j = 0; j < 2; j++) {           // A: 128 rows x 16 k (gathered)
            int i = tid + j * 256;
            int r = i >> 2;
            int kq = (i & 3) << 2;
            float4 v = *(const float4*)(embed + (size_t)rid[r] * DIN + k0 + kq);
            As[kq + 0][r] = v.x; As[kq + 1][r] = v.y;
            As[kq + 2][r] = v.z; As[kq + 3][r] = v.w;
        }
#pragma unroll
        for (int j = 0; j < 2; j++) {           // B: 16 k x 128 n
            int i = tid + j * 256;
            int kr = i >> 5;
            int nq = (i & 31) << 2;
            *(float4*)(&Bs[kr][nq]) = *(const float4*)(W + (size_t)(k0 + kr) * G4 + n0 + nq);
        }
        __syncthreads();
#pragma unroll
        for (int k = 0; k < BKK; k++) {
            float a[8], b[8];
            *(float4*)(a)     = *(const float4*)(&As[k][ty * 8]);
            *(float4*)(a + 4) = *(const float4*)(&As[k][ty * 8 + 4]);
            *(float4*)(b)     = *(const float4*)(&Bs[k][tx * 8]);
            *(float4*)(b + 4) = *(const float4*)(&Bs[k][tx * 8 + 4]);
#pragma unroll
            for (int i = 0; i < 8; i++)
#pragma unroll
                for (int j = 0; j < 8; j++) acc[i][j] += a[i] * b[j];
        }
        __syncthreads();
    }
#pragma unroll
    for (int i = 0; i < 8; i++) {
        int m = m0 + ty * 8 + i;
#pragma unroll
        for (int j = 0; j < 8; j += 4) {
            int n = n0 + tx * 8 + j;
            float4 v;
            v.x = acc[i][j + 0] + bias[n + 0];
            v.y = acc[i][j + 1] + bias[n + 1];
            v.z = acc[i][j + 2] + bias[n + 2];
            v.w = acc[i][j + 3] + bias[n + 3];
            *(float4*)(out + (size_t)m * G4 + n) = v;
        }
    }
}

// ------------------------- LSTM recurrence (persistent, grid-synced) -------------------------
__device__ __forceinline__ void gridsync()
{
    __syncthreads();
    if (threadIdx.x == 0) {
        __threadfence();
        unsigned g = g_bargen;
        unsigned a = atomicAdd(&g_barcnt, 1u);
        if (a == NBLK - 1) {
            g_barcnt = 0;
            __threadfence();
            g_bargen = g + 1;
        } else {
            while (g_bargen == g) { __nanosleep(64); }
        }
        __threadfence();
    }
    __syncthreads();
}

// Block layout: blockIdx.x in [0,128):
//   dir = blk/64, bh = (blk%64)/32 -> 16 batches, dg = blk%32 -> 16 h-dims
// Block owns 64 gate-columns: {g*512 + dg*16 + j : g in 0..3, j in 0..15}
// W_hh slice (512x64 f32 = 128KB) stays in SMEM for all 512 steps.
#define HPAD 520

__global__ __launch_bounds__(256, 1) void k_lstm(const float* __restrict__ Whf,
                                                 const float* __restrict__ Whb)
{
    extern __shared__ float sm[];
    float* Ws  = sm;                       // [512][64]
    float* hsm = Ws + 512 * 64;            // [16][HPAD]
    float* gsm = hsm + 16 * HPAD;          // [16][64]
    float* csm = gsm + 16 * 64;            // [16][16]

    int tid = threadIdx.x;
    int blk = blockIdx.x;
    int dir = blk >> 6;
    int rem = blk & 63;
    int bh  = rem >> 5;
    int dg  = rem & 31;
    int d0  = dg * 16;
    int b0  = bh * 16;
    const float* Whh = dir ? Whb : Whf;
    const float* xw  = g_xw[dir];

    for (int idx = tid; idx < 512 * 64; idx += 256) {
        int k = idx >> 6;
        int cj = idx & 63;
        Ws[idx] = Whh[k * G4 + (cj >> 4) * HH + d0 + (cj & 15)];
    }
    csm[tid] = 0.f;
    // zero my slice of parity-0 h
    {
        int b = tid >> 4, j = tid & 15;
        g_hbuf[0][dir][(b0 + b) * HH + d0 + j] = 0.f;
    }
    __threadfence();
    gridsync();

    int bq = tid >> 5;          // 0..7  (batch pair)
    int cq = tid & 31;          // 0..31 (col pair)
    int ub = tid >> 4;          // 0..15 (update batch)
    int uj = tid & 15;          // 0..15 (update dim)
    int cj0 = 2 * cq, cj1 = 2 * cq + 1;
    int gc0 = (cj0 >> 4) * HH + d0 + (cj0 & 15);
    int gc1 = (cj1 >> 4) * HH + d0 + (cj1 & 15);

    for (int s = 0; s < TT; s++) {
        int p = s & 1;
        // stage h (all 512 dims for my 16 batches)
        const float* hb_g = g_hbuf[p][dir];
        for (int idx = tid; idx < 2048; idx += 256) {
            int b = idx >> 7;
            int kq = (idx & 127) << 2;
            float4 v = *(const float4*)(hb_g + (b0 + b) * HH + kq);
            *(float4*)(&hsm[b * HPAD + kq]) = v;
        }
        __syncthreads();
        int t = dir ? (TT - 1 - s) : s;

        float a00, a01, a10, a11;
        {
            const float* xr0 = xw + (size_t)(t * BB + b0 + 2 * bq) * G4;
            const float* xr1 = xr0 + G4;
            a00 = xr0[gc0]; a01 = xr0[gc1];
            a10 = xr1[gc0]; a11 = xr1[gc1];
        }
        const float2* wp2 = (const float2*)(Ws + 2 * cq);
        const float* h0p = hsm + (2 * bq) * HPAD;
        const float* h1p = h0p + HPAD;
#pragma unroll 8
        for (int k = 0; k < HH; k++) {
            float2 w = wp2[k * 32];
            float hx = h0p[k], hy = h1p[k];
            a00 += hx * w.x; a01 += hx * w.y;
            a10 += hy * w.x; a11 += hy * w.y;
        }
        *(float2*)(&gsm[(2 * bq)     * 64 + 2 * cq]) = make_float2(a00, a01);
        *(float2*)(&gsm[(2 * bq + 1) * 64 + 2 * cq]) = make_float2(a10, a11);
        __syncthreads();
        // gate math + state update
        {
            float gi = gsm[ub * 64 +      uj];
            float gf = gsm[ub * 64 + 16 + uj];
            float gg = gsm[ub * 64 + 32 + uj];
            float go = gsm[ub * 64 + 48 + uj];
            float c  = csm[ub * 16 + uj];
            float si = 1.f / (1.f + __expf(-gi));
            float sf = 1.f / (1.f + __expf(-gf));
            float so = 1.f / (1.f + __expf(-go));
            c = sf * c + si * tanhf(gg);
            csm[ub * 16 + uj] = c;
            float h = so * tanhf(c);
            g_hbuf[p ^ 1][dir][(b0 + ub) * HH + d0 + uj] = h;
            g_hs[dir][((size_t)t * BB + b0 + ub) * HH + d0 + uj] = h;
        }
        __threadfence();
        gridsync();
    }
}

// ------------------------- tag projection -------------------------
__global__ __launch_bounds__(256) void k_tag(const float* __restrict__ Wtag,
                                             const float* __restrict__ btag)
{
    extern __shared__ float sm[];
    float* Wt = sm;                 // [30][1024] (transposed)
    float* hh = Wt + KK * 1024;     // [1024]
    int tid = threadIdx.x;
    for (int idx = tid; idx < 1024 * KK; idx += 256) {
        int d = idx / KK;
        int k = idx - d * KK;
        Wt[k * 1024 + d] = Wtag[idx];
    }
    __syncthreads();
    int w = tid >> 5, lane = tid & 31;
    for (int m = blockIdx.x; m < MTOT; m += gridDim.x) {
        int t = m >> 5, b = m & 31;
        {
            int hidx = tid;   // 256 float4 = 1024 floats
            const float* src = (hidx < 128)
                ? (g_hs[0] + ((size_t)t * BB + b) * HH + hidx * 4)
                : (g_hs[1] + ((size_t)t * BB + b) * HH + (hidx - 128) * 4);
            *(float4*)(&hh[hidx * 4]) = *(const float4*)src;
        }
        __syncthreads();
#pragma unroll
        for (int q = 0; q < 4; q++) {
            int k = w + q * 8;
            if (k < KK) {
                const float* wr = Wt + k * 1024;
                float s = 0.f;
#pragma unroll
                for (int i = 0; i < 8; i++) {
                    int d = lane * 4 + i * 128;
                    float4 hv = *(const float4*)(&hh[d]);
                    float4 wv = *(const float4*)(&wr[d]);
                    s += hv.x * wv.x + hv.y * wv.y + hv.z * wv.z + hv.w * wv.w;
                }
#pragma unroll
                for (int off = 16; off; off >>= 1)
                    s += __shfl_down_sync(0xffffffffu, s, off);
                if (lane == 0)
                    g_feats[((size_t)b * TT + t) * KK + k] = s + btag[k];
            }
        }
        __syncthreads();
    }
}

// ------------------------- CRF NLL (one warp per sentence) -------------------------
__global__ void k_crf(const float* __restrict__ trans, const int* __restrict__ tags,
                      float* __restrict__ out)
{
    int b = blockIdx.x;
    int lane = threadIdx.x;
    float trow[KK];
    int lr = (lane < KK) ? lane : 0;
#pragma unroll
    for (int p = 0; p < KK; p++) trow[p] = trans[lr * KK + p];
    float alpha = (lane == TSTART) ? 0.f : NEGV;
    const float* fb = g_feats + (size_t)b * TT * KK;
    for (int t = 0; t < TT; t++) {
        float emit = (lane < KK) ? fb[t * KK + lane] : 0.f;
        float v[KK];
        float vmax = -1e30f;
#pragma unroll
        for (int p = 0; p < KK; p++) {
            v[p] = __shfl_sync(0xffffffffu, alpha, p) + trow[p];
            vmax = fmaxf(vmax, v[p]);
        }
        float ssum = 0.f;
#pragma unroll
        for (int p = 0; p < KK; p++) ssum += __expf(v[p] - vmax);
        float na = vmax + __logf(ssum) + emit;
        alpha = (lane < KK) ? na : NEGV;
    }
    // log_z
    float v = (lane < KK) ? (alpha + trans[TSTOP * KK + lane]) : -1e30f;
    float m = v;
#pragma unroll
    for (int off = 16; off; off >>= 1) m = fmaxf(m, __shfl_xor_sync(0xffffffffu, m, off));
    float e = (lane < KK) ? __expf(v - m) : 0.f;
#pragma unroll
    for (int off = 16; off; off >>= 1) e += __shfl_xor_sync(0xffffffffu, e, off);
    float logz = m + __logf(e);
    // gold score
    const int* tg = tags + b * TT;
    float gold = 0.f;
    for (int j = lane; j < TT + 1; j += 32) {
        int prev = (j == 0) ? TSTART : tg[j - 1];
        int nxt  = (j < TT) ? tg[j] : TSTOP;
        gold += trans[nxt * KK + prev];
        if (j < TT) gold += fb[j * KK + tg[j]];
    }
#pragma unroll
    for (int off = 16; off; off >>= 1) gold += __shfl_xor_sync(0xffffffffu, gold, off);
    if (lane == 0) out[b] = logz - gold;
}

// ------------------------- launcher -------------------------
extern "C" void kernel_launch(void* const* d_in, const int* in_sizes, int n_in,
                              void* d_out, int out_size)
{
    const int*   ids   = (const int*)  d_in[0];
    const int*   tags  = (const int*)  d_in[1];
    const float* embed = (const float*)d_in[2];
    const float* Wihf  = (const float*)d_in[3];
    const float* Whhf  = (const float*)d_in[4];
    const float* bf    = (const float*)d_in[5];
    const float* Wihb  = (const float*)d_in[6];
    const float* Whhb  = (const float*)d_in[7];
    const float* bb    = (const float*)d_in[8];
    const float* Wtag  = (const float*)d_in[9];
    const float* btag  = (const float*)d_in[10];
    const float* trans = (const float*)d_in[11];
    float* out = (float*)d_out;

    size_t lsm = (size_t)(512 * 64 + 16 * HPAD + 16 * 64 + 16 * 16) * sizeof(float);
    size_t tsm = (size_t)(KK * 1024 + 1024) * sizeof(float);
    cudaFuncSetAttribute(k_lstm, cudaFuncAttributeMaxDynamicSharedMemorySize, (int)lsm);
    cudaFuncSetAttribute(k_tag,  cudaFuncAttributeMaxDynamicSharedMemorySize, (int)tsm);

    dim3 gg(G4 / BN, MTOT / BM);
    k_gemm<<<gg, 256>>>(embed, ids, Wihf, bf, 0);
    k_gemm<<<gg, 256>>>(embed, ids, Wihb, bb, 1);
    k_lstm<<<NBLK, 256, lsm>>>(Whhf, Whhb);
    k_tag<<<148, 256, tsm>>>(Wtag, btag);
    k_crf<<<BB, 32>>>(trans, tags, out);
}

// round 2
// speedup vs baseline: 1.6630x; 1.6630x over previous
#include <cuda_runtime.h>
#include <cuda_bf16.h>
#include <math.h>

#define BB 32
#define TT 512
#define DIN 1824
#define HH 512
#define G4 2048
#define KK 30
#define TSTART 28
#define TSTOP 29
#define NEGV (-10000.0f)
#define MTOT (TT*BB)            /* 16384 */
#define NBLK 128

// ------------------------- device scratch -------------------------
__device__ float g_xw[2][(size_t)MTOT*G4];      // [dir][m][4H], m = t*B+b
__device__ float g_hs[2][(size_t)MTOT*HH];      // hf/hb, [t][b][d]
__device__ float g_hbuf[2][2][BB*HH];           // [parity][dir][b][d]
__device__ float g_feats[(size_t)BB*TT*KK];     // [b][t][k]
__device__ __nv_bfloat16 g_xb[(size_t)MTOT*DIN];     // gathered embeddings, bf16
__device__ __nv_bfloat16 g_wb[2][(size_t)DIN*G4];    // W_ih f/b, bf16
__device__ unsigned g_barcnt = 0;
__device__ volatile unsigned g_bargen = 0;

__device__ __forceinline__ unsigned smaddr(const void* p)
{
    return (unsigned)__cvta_generic_to_shared(p);
}

// ------------------------- bf16 cast kernels -------------------------
__global__ __launch_bounds__(256) void k_castx(const float* __restrict__ embed,
                                               const int* __restrict__ ids)
{
    size_t idx = (size_t)blockIdx.x * 256 + threadIdx.x;   // over MTOT*456
    if (idx >= (size_t)MTOT * (DIN / 4)) return;
    int m = (int)(idx / (DIN / 4));
    int q = (int)(idx % (DIN / 4));
    int id = ids[(m & 31) * TT + (m >> 5)];
    float4 v = *(const float4*)(embed + (size_t)id * DIN + 4 * q);
    __nv_bfloat162 lo = __floats2bfloat162_rn(v.x, v.y);
    __nv_bfloat162 hi = __floats2bfloat162_rn(v.z, v.w);
    uint2 pk;
    pk.x = *(unsigned*)&lo;
    pk.y = *(unsigned*)&hi;
    *(uint2*)(g_xb + (size_t)m * DIN + 4 * q) = pk;
}

__global__ __launch_bounds__(256) void k_castw(const float* __restrict__ W, int dir)
{
    size_t idx = (size_t)blockIdx.x * 256 + threadIdx.x;   // over DIN*G4/4
    if (idx >= (size_t)DIN * G4 / 4) return;
    float4 v = *(const float4*)(W + 4 * idx);
    __nv_bfloat162 lo = __floats2bfloat162_rn(v.x, v.y);
    __nv_bfloat162 hi = __floats2bfloat162_rn(v.z, v.w);
    uint2 pk;
    pk.x = *(unsigned*)&lo;
    pk.y = *(unsigned*)&hi;
    *(uint2*)(g_wb[dir] + 4 * idx) = pk;
}

// ------------------------- bf16 tensor-core GEMM -------------------------
// C[m][n] = sum_k xb[m][k] * wb[k][n] + bias[n],  M=16384, N=2048, K=1824
#define BM 128
#define BN 128
#define BK 32
#define APAD 8
#define BPAD 8
#define NKT (DIN / BK)   /* 57 */

__global__ __launch_bounds__(256) void k_gemm(const float* __restrict__ bias, int dir)
{
    __shared__ __nv_bfloat16 As[2][BM][BK + APAD];   // 20.5 KB
    __shared__ __nv_bfloat16 Bs[2][BK][BN + BPAD];   // 17.4 KB

    const __nv_bfloat16* A = g_xb;
    const __nv_bfloat16* Bw = g_wb[dir];
    float* out = g_xw[dir];

    int tid = threadIdx.x;
    int wid = tid >> 5;
    int lane = tid & 31;
    int m0 = blockIdx.y * BM;
    int n0 = blockIdx.x * BN;
    int wm = (wid & 3) * 32;       // warp m offset (4 warps down)
    int wn = (wid >> 2) * 64;      // warp n offset (2 warps across)

    float acc[2][8][4];
#pragma unroll
    for (int i = 0; i < 2; i++)
#pragma unroll
        for (int j = 0; j < 8; j++)
#pragma unroll
            for (int r = 0; r < 4; r++) acc[i][j][r] = 0.f;

    // cp.async tile loaders
    auto loadA = [&](int buf, int k0) {
#pragma unroll
        for (int j = 0; j < 2; j++) {
            int c = tid + j * 256;          // 512 chunks of 16B
            int r = c >> 2, q = c & 3;
            unsigned dst = smaddr(&As[buf][r][q * 8]);
            const __nv_bfloat16* src = A + (size_t)(m0 + r) * DIN + k0 + q * 8;
            asm volatile("cp.async.cg.shared.global [%0], [%1], 16;\n" :: "r"(dst), "l"(src));
        }
    };
    auto loadB = [&](int buf, int k0) {
#pragma unroll
        for (int j = 0; j < 2; j++) {
            int c = tid + j * 256;
            int r = c >> 4, q = c & 15;
            unsigned dst = smaddr(&Bs[buf][r][q * 8]);
            const __nv_bfloat16* src = Bw + (size_t)(k0 + r) * G4 + n0 + q * 8;
            asm volatile("cp.async.cg.shared.global [%0], [%1], 16;\n" :: "r"(dst), "l"(src));
        }
    };

    loadA(0, 0);
    loadB(0, 0);
    asm volatile("cp.async.commit_group;\n");

    for (int kt = 0; kt < NKT; kt++) {
        int buf = kt & 1;
        if (kt + 1 < NKT) {
            loadA(buf ^ 1, (kt + 1) * BK);
            loadB(buf ^ 1, (kt + 1) * BK);
            asm volatile("cp.async.commit_group;\n");
            asm volatile("cp.async.wait_group 1;\n");
        } else {
            asm volatile("cp.async.wait_group 0;\n");
        }
        __syncthreads();

#pragma unroll
        for (int ks = 0; ks < 2; ks++) {     // two k16 sub-tiles
            int k0 = ks * 16;
            unsigned a[2][4];
#pragma unroll
            for (int mi = 0; mi < 2; mi++) {
                unsigned addr = smaddr(&As[buf][wm + mi * 16 + (lane & 15)][k0 + 8 * (lane >> 4)]);
                asm volatile("ldmatrix.sync.aligned.m8n8.x4.shared.b16 {%0,%1,%2,%3}, [%4];\n"
                             : "=r"(a[mi][0]), "=r"(a[mi][1]), "=r"(a[mi][2]), "=r"(a[mi][3])
                             : "r"(addr));
            }
            unsigned b[4][4];
#pragma unroll
            for (int nj = 0; nj < 4; nj++) {  // each covers n16
                unsigned addr = smaddr(&Bs[buf][k0 + (lane & 15)][wn + nj * 16 + 8 * (lane >> 4)]);
                asm volatile("ldmatrix.sync.aligned.m8n8.x4.trans.shared.b16 {%0,%1,%2,%3}, [%4];\n"
                             : "=r"(b[nj][0]), "=r"(b[nj][1]), "=r"(b[nj][2]), "=r"(b[nj][3])
                             : "r"(addr));
            }
#pragma unroll
            for (int mi = 0; mi < 2; mi++)
#pragma unroll
                for (int ni = 0; ni < 8; ni++) {
                    unsigned b0 = b[ni >> 1][(ni & 1) * 2];
                    unsigned b1 = b[ni >> 1][(ni & 1) * 2 + 1];
                    asm volatile(
                        "mma.sync.aligned.m16n8k16.row.col.f32.bf16.bf16.f32 "
                        "{%0,%1,%2,%3}, {%4,%5,%6,%7}, {%8,%9}, {%0,%1,%2,%3};\n"
                        : "+f"(acc[mi][ni][0]), "+f"(acc[mi][ni][1]),
                          "+f"(acc[mi][ni][2]), "+f"(acc[mi][ni][3])
                        : "r"(a[mi][0]), "r"(a[mi][1]), "r"(a[mi][2]), "r"(a[mi][3]),
                          "r"(b0), "r"(b1));
                }
        }
        __syncthreads();
    }

    // epilogue: add bias, store fp32
#pragma unroll
    for (int mi = 0; mi < 2; mi++) {
#pragma unroll
        for (int ni = 0; ni < 8; ni++) {
            int col = n0 + wn + ni * 8 + (lane & 3) * 2;
            float bx = bias[col], by = bias[col + 1];
            int row0 = m0 + wm + mi * 16 + (lane >> 2);
            float2 v0 = make_float2(acc[mi][ni][0] + bx, acc[mi][ni][1] + by);
            float2 v1 = make_float2(acc[mi][ni][2] + bx, acc[mi][ni][3] + by);
            *(float2*)(out + (size_t)row0 * G4 + col) = v0;
            *(float2*)(out + (size_t)(row0 + 8) * G4 + col) = v1;
        }
    }
}

// ------------------------- LSTM recurrence (persistent, grid-synced) -------------------------
__device__ __forceinline__ void gridsync()
{
    __syncthreads();
    if (threadIdx.x == 0) {
        __threadfence();
        unsigned g = g_bargen;
        unsigned a = atomicAdd(&g_barcnt, 1u);
        if (a == NBLK - 1) {
            g_barcnt = 0;
            __threadfence();
            g_bargen = g + 1;
        } else {
            while (g_bargen == g) { __nanosleep(64); }
        }
        __threadfence();
    }
    __syncthreads();
}

#define HPAD 520

__global__ __launch_bounds__(256, 1) void k_lstm(const float* __restrict__ Whf,
                                                 const float* __restrict__ Whb)
{
    extern __shared__ float sm[];
    float* Ws  = sm;                       // [512][64]
    float* hsm = Ws + 512 * 64;            // [16][HPAD]
    float* gsm = hsm + 16 * HPAD;          // [16][64]
    float* csm = gsm + 16 * 64;            // [16][16]

    int tid = threadIdx.x;
    int blk = blockIdx.x;
    int dir = blk >> 6;
    int rem = blk & 63;
    int bh  = rem >> 5;
    int dg  = rem & 31;
    int d0  = dg * 16;
    int b0  = bh * 16;
    const float* Whh = dir ? Whb : Whf;
    const float* xw  = g_xw[dir];

    for (int idx = tid; idx < 512 * 64; idx += 256) {
        int k = idx >> 6;
        int cj = idx & 63;
        Ws[idx] = Whh[k * G4 + (cj >> 4) * HH + d0 + (cj & 15)];
    }
    csm[tid] = 0.f;
    {
        int b = tid >> 4, j = tid & 15;
        g_hbuf[0][dir][(b0 + b) * HH + d0 + j] = 0.f;
    }
    __threadfence();
    gridsync();

    int bq = tid >> 5;
    int cq = tid & 31;
    int ub = tid >> 4;
    int uj = tid & 15;
    int cj0 = 2 * cq, cj1 = 2 * cq + 1;
    int gc0 = (cj0 >> 4) * HH + d0 + (cj0 & 15);
    int gc1 = (cj1 >> 4) * HH + d0 + (cj1 & 15);

    for (int s = 0; s < TT; s++) {
        int p = s & 1;
        const float* hb_g = g_hbuf[p][dir];
        for (int idx = tid; idx < 2048; idx += 256) {
            int b = idx >> 7;
            int kq = (idx & 127) << 2;
            float4 v = *(const float4*)(hb_g + (b0 + b) * HH + kq);
            *(float4*)(&hsm[b * HPAD + kq]) = v;
        }
        __syncthreads();
        int t = dir ? (TT - 1 - s) : s;

        float a00, a01, a10, a11;
        {
            const float* xr0 = xw + (size_t)(t * BB + b0 + 2 * bq) * G4;
            const float* xr1 = xr0 + G4;
            a00 = xr0[gc0]; a01 = xr0[gc1];
            a10 = xr1[gc0]; a11 = xr1[gc1];
        }
        const float2* wp2 = (const float2*)(Ws + 2 * cq);
        const float* h0p = hsm + (2 * bq) * HPAD;
        const float* h1p = h0p + HPAD;
#pragma unroll 8
        for (int k = 0; k < HH; k++) {
            float2 w = wp2[k * 32];
            float hx = h0p[k], hy = h1p[k];
            a00 += hx * w.x; a01 += hx * w.y;
            a10 += hy * w.x; a11 += hy * w.y;
        }
        *(float2*)(&gsm[(2 * bq)     * 64 + 2 * cq]) = make_float2(a00, a01);
        *(float2*)(&gsm[(2 * bq + 1) * 64 + 2 * cq]) = make_float2(a10, a11);
        __syncthreads();
        {
            float gi = gsm[ub * 64 +      uj];
            float gf = gsm[ub * 64 + 16 + uj];
            float gg = gsm[ub * 64 + 32 + uj];
            float go = gsm[ub * 64 + 48 + uj];
            float c  = csm[ub * 16 + uj];
            float si = 1.f / (1.f + __expf(-gi));
            float sf = 1.f / (1.f + __expf(-gf));
            float so = 1.f / (1.f + __expf(-go));
            c = sf * c + si * tanhf(gg);
            csm[ub * 16 + uj] = c;
            float h = so * tanhf(c);
            g_hbuf[p ^ 1][dir][(b0 + ub) * HH + d0 + uj] = h;
            g_hs[dir][((size_t)t * BB + b0 + ub) * HH + d0 + uj] = h;
        }
        __threadfence();
        gridsync();
    }
}

// ------------------------- tag projection -------------------------
__global__ __launch_bounds__(256) void k_tag(const float* __restrict__ Wtag,
                                             const float* __restrict__ btag)
{
    extern __shared__ float sm[];
    float* Wt = sm;                 // [30][1024] (transposed)
    float* hh = Wt + KK * 1024;     // [1024]
    int tid = threadIdx.x;
    for (int idx = tid; idx < 1024 * KK; idx += 256) {
        int d = idx / KK;
        int k = idx - d * KK;
        Wt[k * 1024 + d] = Wtag[idx];
    }
    __syncthreads();
    int w = tid >> 5, lane = tid & 31;
    for (int m = blockIdx.x; m < MTOT; m += gridDim.x) {
        int t = m >> 5, b = m & 31;
        {
            int hidx = tid;
            const float* src = (hidx < 128)
                ? (g_hs[0] + ((size_t)t * BB + b) * HH + hidx * 4)
                : (g_hs[1] + ((size_t)t * BB + b) * HH + (hidx - 128) * 4);
            *(float4*)(&hh[hidx * 4]) = *(const float4*)src;
        }
        __syncthreads();
#pragma unroll
        for (int q = 0; q < 4; q++) {
            int k = w + q * 8;
            if (k < KK) {
                const float* wr = Wt + k * 1024;
                float s = 0.f;
#pragma unroll
                for (int i = 0; i < 8; i++) {
                    int d = lane * 4 + i * 128;
                    float4 hv = *(const float4*)(&hh[d]);
                    float4 wv = *(const float4*)(&wr[d]);
                    s += hv.x * wv.x + hv.y * wv.y + hv.z * wv.z + hv.w * wv.w;
                }
#pragma unroll
                for (int off = 16; off; off >>= 1)
                    s += __shfl_down_sync(0xffffffffu, s, off);
                if (lane == 0)
                    g_feats[((size_t)b * TT + t) * KK + k] = s + btag[k];
            }
        }
        __syncthreads();
    }
}

// ------------------------- CRF NLL (one warp per sentence) -------------------------
__global__ void k_crf(const float* __restrict__ trans, const int* __restrict__ tags,
                      float* __restrict__ out)
{
    int b = blockIdx.x;
    int lane = threadIdx.x;
    float trow[KK];
    int lr = (lane < KK) ? lane : 0;
#pragma unroll
    for (int p = 0; p < KK; p++) trow[p] = trans[lr * KK + p];
    float alpha = (lane == TSTART) ? 0.f : NEGV;
    const float* fb = g_feats + (size_t)b * TT * KK;
    for (int t = 0; t < TT; t++) {
        float emit = (lane < KK) ? fb[t * KK + lane] : 0.f;
        float v[KK];
        float vmax = -1e30f;
#pragma unroll
        for (int p = 0; p < KK; p++) {
            v[p] = __shfl_sync(0xffffffffu, alpha, p) + trow[p];
            vmax = fmaxf(vmax, v[p]);
        }
        float ssum = 0.f;
#pragma unroll
        for (int p = 0; p < KK; p++) ssum += __expf(v[p] - vmax);
        float na = vmax + __logf(ssum) + emit;
        alpha = (lane < KK) ? na : NEGV;
    }
    float v = (lane < KK) ? (alpha + trans[TSTOP * KK + lane]) : -1e30f;
    float m = v;
#pragma unroll
    for (int off = 16; off; off >>= 1) m = fmaxf(m, __shfl_xor_sync(0xffffffffu, m, off));
    float e = (lane < KK) ? __expf(v - m) : 0.f;
#pragma unroll
    for (int off = 16; off; off >>= 1) e += __shfl_xor_sync(0xffffffffu, e, off);
    float logz = m + __logf(e);
    const int* tg = tags + b * TT;
    float gold = 0.f;
    for (int j = lane; j < TT + 1; j += 32) {
        int prev = (j == 0) ? TSTART : tg[j - 1];
        int nxt  = (j < TT) ? tg[j] : TSTOP;
        gold += trans[nxt * KK + prev];
        if (j < TT) gold += fb[j * KK + tg[j]];
    }
#pragma unroll
    for (int off = 16; off; off >>= 1) gold += __shfl_xor_sync(0xffffffffu, gold, off);
    if (lane == 0) out[b] = logz - gold;
}

// ------------------------- launcher -------------------------
extern "C" void kernel_launch(void* const* d_in, const int* in_sizes, int n_in,
                              void* d_out, int out_size)
{
    const int*   ids   = (const int*)  d_in[0];
    const int*   tags  = (const int*)  d_in[1];
    const float* embed = (const float*)d_in[2];
    const float* Wihf  = (const float*)d_in[3];
    const float* Whhf  = (const float*)d_in[4];
    const float* bf    = (const float*)d_in[5];
    const float* Wihb  = (const float*)d_in[6];
    const float* Whhb  = (const float*)d_in[7];
    const float* bb    = (const float*)d_in[8];
    const float* Wtag  = (const float*)d_in[9];
    const float* btag  = (const float*)d_in[10];
    const float* trans = (const float*)d_in[11];
    float* out = (float*)d_out;

    size_t lsm = (size_t)(512 * 64 + 16 * HPAD + 16 * 64 + 16 * 16) * sizeof(float);
    size_t tsm = (size_t)(KK * 1024 + 1024) * sizeof(float);
    cudaFuncSetAttribute(k_lstm, cudaFuncAttributeMaxDynamicSharedMemorySize, (int)lsm);
    cudaFuncSetAttribute(k_tag,  cudaFuncAttributeMaxDynamicSharedMemorySize, (int)tsm);

    {
        size_t nx = (size_t)MTOT * (DIN / 4);
        k_castx<<<(unsigned)((nx + 255) / 256), 256>>>(embed, ids);
        size_t nw = (size_t)DIN * G4 / 4;
        k_castw<<<(unsigned)((nw + 255) / 256), 256>>>(Wihf, 0);
        k_castw<<<(unsigned)((nw + 255) / 256), 256>>>(Wihb, 1);
    }

    dim3 gg(G4 / BN, MTOT / BM);
    k_gemm<<<gg, 256>>>(bf, 0);
    k_gemm<<<gg, 256>>>(bb, 1);
    k_lstm<<<NBLK, 256, lsm>>>(Whhf, Whhb);
    k_tag<<<148, 256, tsm>>>(Wtag, btag);
    k_crf<<<BB, 32>>>(trans, tags, out);
}

// round 3
// speedup vs baseline: 3.7824x; 2.2744x over previous
#include <cuda_runtime.h>
#include <cuda_bf16.h>
#include <math.h>

#define BB 32
#define TT 512
#define DIN 1824
#define HH 512
#define G4 2048
#define KK 30
#define TSTART 28
#define TSTOP 29
#define NEGV (-10000.0f)
#define MTOT (TT*BB)            /* 16384 */

// ------------------------- device scratch -------------------------
__device__ float g_xw[2][(size_t)MTOT*G4];      // [dir][m][4H], m = t*B+b
__device__ float g_hs[2][(size_t)MTOT*HH];      // hf/hb, [t][b][d]
__device__ float g_feats[(size_t)BB*TT*KK];     // [b][t][k]
__device__ __nv_bfloat16 g_xb[(size_t)MTOT*DIN];     // gathered embeddings, bf16
__device__ __nv_bfloat16 g_wb[2][(size_t)DIN*G4];    // W_ih f/b, bf16
__device__ __nv_bfloat16 g_wb2[2][(size_t)HH*G4];    // W_hh f/b, bf16
__device__ __nv_bfloat16 g_hex[2][2][2][16*HH];      // [dir][bgrp][parity][b][k] h exchange

__device__ __forceinline__ unsigned smaddr(const void* p)
{
    return (unsigned)__cvta_generic_to_shared(p);
}

// ------------------------- bf16 cast kernels -------------------------
__global__ __launch_bounds__(256) void k_castx(const float* __restrict__ embed,
                                               const int* __restrict__ ids)
{
    size_t idx = (size_t)blockIdx.x * 256 + threadIdx.x;   // over MTOT*456
    if (idx >= (size_t)MTOT * (DIN / 4)) return;
    int m = (int)(idx / (DIN / 4));
    int q = (int)(idx % (DIN / 4));
    int id = ids[(m & 31) * TT + (m >> 5)];
    float4 v = *(const float4*)(embed + (size_t)id * DIN + 4 * q);
    __nv_bfloat162 lo = __floats2bfloat162_rn(v.x, v.y);
    __nv_bfloat162 hi = __floats2bfloat162_rn(v.z, v.w);
    uint2 pk; pk.x = *(unsigned*)&lo; pk.y = *(unsigned*)&hi;
    *(uint2*)(g_xb + (size_t)m * DIN + 4 * q) = pk;
}

__global__ __launch_bounds__(256) void k_cast(const float* __restrict__ src,
                                              __nv_bfloat16* __restrict__ dst,
                                              size_t n4)
{
    size_t idx = (size_t)blockIdx.x * 256 + threadIdx.x;
    if (idx >= n4) return;
    float4 v = *(const float4*)(src + 4 * idx);
    __nv_bfloat162 lo = __floats2bfloat162_rn(v.x, v.y);
    __nv_bfloat162 hi = __floats2bfloat162_rn(v.z, v.w);
    uint2 pk; pk.x = *(unsigned*)&lo; pk.y = *(unsigned*)&hi;
    *(uint2*)(dst + 4 * idx) = pk;
}

// ------------------------- bf16 tensor-core input GEMM -------------------------
#define BM 128
#define BN 128
#define BK 32
#define APAD 8
#define BPAD 8
#define NKT (DIN / BK)   /* 57 */

__global__ __launch_bounds__(256) void k_gemm(const float* __restrict__ bias, int dir)
{
    __shared__ __nv_bfloat16 As[2][BM][BK + APAD];
    __shared__ __nv_bfloat16 Bs[2][BK][BN + BPAD];

    const __nv_bfloat16* A = g_xb;
    const __nv_bfloat16* Bw = g_wb[dir];
    float* out = g_xw[dir];

    int tid = threadIdx.x;
    int wid = tid >> 5;
    int lane = tid & 31;
    int m0 = blockIdx.y * BM;
    int n0 = blockIdx.x * BN;
    int wm = (wid & 3) * 32;
    int wn = (wid >> 2) * 64;

    float acc[2][8][4];
#pragma unroll
    for (int i = 0; i < 2; i++)
#pragma unroll
        for (int j = 0; j < 8; j++)
#pragma unroll
            for (int r = 0; r < 4; r++) acc[i][j][r] = 0.f;

    auto loadA = [&](int buf, int k0) {
#pragma unroll
        for (int j = 0; j < 2; j++) {
            int c = tid + j * 256;
            int r = c >> 2, q = c & 3;
            unsigned dst = smaddr(&As[buf][r][q * 8]);
            const __nv_bfloat16* src = A + (size_t)(m0 + r) * DIN + k0 + q * 8;
            asm volatile("cp.async.cg.shared.global [%0], [%1], 16;\n" :: "r"(dst), "l"(src));
        }
    };
    auto loadB = [&](int buf, int k0) {
#pragma unroll
        for (int j = 0; j < 2; j++) {
            int c = tid + j * 256;
            int r = c >> 4, q = c & 15;
            unsigned dst = smaddr(&Bs[buf][r][q * 8]);
            const __nv_bfloat16* src = Bw + (size_t)(k0 + r) * G4 + n0 + q * 8;
            asm volatile("cp.async.cg.shared.global [%0], [%1], 16;\n" :: "r"(dst), "l"(src));
        }
    };

    loadA(0, 0); loadB(0, 0);
    asm volatile("cp.async.commit_group;\n");

    for (int kt = 0; kt < NKT; kt++) {
        int buf = kt & 1;
        if (kt + 1 < NKT) {
            loadA(buf ^ 1, (kt + 1) * BK);
            loadB(buf ^ 1, (kt + 1) * BK);
            asm volatile("cp.async.commit_group;\n");
            asm volatile("cp.async.wait_group 1;\n");
        } else {
            asm volatile("cp.async.wait_group 0;\n");
        }
        __syncthreads();

#pragma unroll
        for (int ks = 0; ks < 2; ks++) {
            int k0 = ks * 16;
            unsigned a[2][4];
#pragma unroll
            for (int mi = 0; mi < 2; mi++) {
                unsigned addr = smaddr(&As[buf][wm + mi * 16 + (lane & 15)][k0 + 8 * (lane >> 4)]);
                asm volatile("ldmatrix.sync.aligned.m8n8.x4.shared.b16 {%0,%1,%2,%3}, [%4];\n"
                             : "=r"(a[mi][0]), "=r"(a[mi][1]), "=r"(a[mi][2]), "=r"(a[mi][3])
                             : "r"(addr));
            }
            unsigned b[4][4];
#pragma unroll
            for (int nj = 0; nj < 4; nj++) {
                unsigned addr = smaddr(&Bs[buf][k0 + (lane & 15)][wn + nj * 16 + 8 * (lane >> 4)]);
                asm volatile("ldmatrix.sync.aligned.m8n8.x4.trans.shared.b16 {%0,%1,%2,%3}, [%4];\n"
                             : "=r"(b[nj][0]), "=r"(b[nj][1]), "=r"(b[nj][2]), "=r"(b[nj][3])
                             : "r"(addr));
            }
#pragma unroll
            for (int mi = 0; mi < 2; mi++)
#pragma unroll
                for (int ni = 0; ni < 8; ni++) {
                    unsigned b0 = b[ni >> 1][(ni & 1) * 2];
                    unsigned b1 = b[ni >> 1][(ni & 1) * 2 + 1];
                    asm volatile(
                        "mma.sync.aligned.m16n8k16.row.col.f32.bf16.bf16.f32 "
                        "{%0,%1,%2,%3}, {%4,%5,%6,%7}, {%8,%9}, {%0,%1,%2,%3};\n"
                        : "+f"(acc[mi][ni][0]), "+f"(acc[mi][ni][1]),
                          "+f"(acc[mi][ni][2]), "+f"(acc[mi][ni][3])
                        : "r"(a[mi][0]), "r"(a[mi][1]), "r"(a[mi][2]), "r"(a[mi][3]),
                          "r"(b0), "r"(b1));
                }
        }
        __syncthreads();
    }

#pragma unroll
    for (int mi = 0; mi < 2; mi++) {
#pragma unroll
        for (int ni = 0; ni < 8; ni++) {
            int col = n0 + wn + ni * 8 + (lane & 3) * 2;
            float bx = bias[col], by = bias[col + 1];
            int row0 = m0 + wm + mi * 16 + (lane >> 2);
            float2 v0 = make_float2(acc[mi][ni][0] + bx, acc[mi][ni][1] + by);
            float2 v1 = make_float2(acc[mi][ni][2] + bx, acc[mi][ni][3] + by);
            *(float2*)(out + (size_t)row0 * G4 + col) = v0;
            *(float2*)(out + (size_t)(row0 + 8) * G4 + col) = v1;
        }
    }
}

// ------------------------- LSTM recurrence: 4 clusters of 16 CTAs -------------------------
// Cluster c: dir = c>>1, batch-group bg = c&1 (16 batches). CTA rank r owns h-dims
// [32r, 32r+32) x 4 gates = 128 gate columns; W_hh slice (512x128 bf16, +pad) resident
// in SMEM. Per step: pull h (16x512 bf16) from L2 via cp.async.cg, mma (warps: 4 n-groups
// x 2 k-halves), reduce k-halves in SMEM, gate math fp32, publish h via __stcg, cluster.sync.
#define WPAD 136            /* 128 + 8 bf16 pad */
#define SPAD 520            /* 512 + 8 bf16 pad */

#define LSM_W      0
#define LSM_STAGE  (512*WPAD)                 /* bf16 elems */
#define LSM_GATES  ((LSM_STAGE + 16*SPAD))    /* float, offset in bf16 elems /2 */
#define LSM_BYTES  (512*WPAD*2 + 16*SPAD*2 + 16*128*4 + 512*4)

__global__ __launch_bounds__(256, 1) __cluster_dims__(16, 1, 1)
void k_lstm2(void)
{
    extern __shared__ char smraw[];
    __nv_bfloat16* Ws   = (__nv_bfloat16*)smraw;                       // [512][136]
    __nv_bfloat16* Astg = Ws + 512 * WPAD;                             // [16][520]
    float*         gates = (float*)(Astg + 16 * SPAD);                 // [16][128]
    float*         csm   = gates + 16 * 128;                           // [16][32]

    int tid = threadIdx.x;
    int wid = tid >> 5;
    int lane = tid & 31;
    int cid = blockIdx.x >> 4;          // cluster id
    int rank = blockIdx.x & 15;
    int dir = cid >> 1;
    int bg  = cid & 1;
    int j0  = rank * 32;

    const __nv_bfloat16* Whh = g_wb2[dir];
    const float* xw = g_xw[dir];
    float* hs = g_hs[dir];

    // load W slice: cols {q*512 + j0 + j : q<4, j<32} -> Ws[k][q*32+j]
    for (int c = tid; c < 512 * 16; c += 256) {
        int k = c >> 4, ch = c & 15;
        int q = ch >> 2, jb = (ch & 3) * 8;
        uint4 v = *(const uint4*)(Whh + (size_t)k * G4 + q * 512 + j0 + jb);
        *(uint4*)(Ws + k * WPAD + q * 32 + jb) = v;
    }
    // zero staging (h0 = 0) and c
    for (int c = tid; c < 16 * SPAD / 4; c += 256) ((uint2*)Astg)[c] = make_uint2(0, 0);
    if (tid < 512) csm[tid] = 0.f;   // 256 threads: do twice
    csm[256 + tid >= 512 ? tid : 256 + tid] = 0.f;
    __syncthreads();

    int kh = wid & 1;          // k half
    int ng = wid >> 1;         // n group (32 cols)
    int kbase = kh * 256;
    int ngc = ng * 32;

    for (int s = 0; s < TT; s++) {
        int t = dir ? (TT - 1 - s) : s;
        // pull h(s) from exchange buffer (skip on s=0: staging pre-zeroed)
        if (s) {
            const __nv_bfloat16* hx = g_hex[dir][bg][s & 1];
#pragma unroll
            for (int i = 0; i < 4; i++) {
                int c = tid + i * 256;
                int row = c >> 6, cq = c & 63;
                unsigned dst = smaddr(Astg + row * SPAD + cq * 8);
                const __nv_bfloat16* src = hx + row * HH + cq * 8;
                asm volatile("cp.async.cg.shared.global [%0], [%1], 16;\n" :: "r"(dst), "l"(src));
            }
            asm volatile("cp.async.commit_group;\n");
        }
        // prefetch xw for gate math (thread -> (b, jp, jp+1))
        int gb = tid >> 4;
        int jp = (tid & 15) * 2;
        const float* xrow = xw + (size_t)(t * BB + bg * 16 + gb) * G4 + j0 + jp;
        float2 xq0 = *(const float2*)(xrow);
        float2 xq1 = *(const float2*)(xrow + 512);
        float2 xq2 = *(const float2*)(xrow + 1024);
        float2 xq3 = *(const float2*)(xrow + 1536);

        asm volatile("cp.async.wait_group 0;\n");
        __syncthreads();

        // mma: M=16, N=32 (ng), K=256 (kh)
        float acc[4][4];
#pragma unroll
        for (int i = 0; i < 4; i++)
#pragma unroll
            for (int j = 0; j < 4; j++) acc[i][j] = 0.f;

#pragma unroll 4
        for (int kk = 0; kk < 16; kk++) {
            int k0 = kbase + kk * 16;
            unsigned a[4];
            {
                unsigned addr = smaddr(Astg + (lane & 15) * SPAD + k0 + 8 * (lane >> 4));
                asm volatile("ldmatrix.sync.aligned.m8n8.x4.shared.b16 {%0,%1,%2,%3}, [%4];\n"
                             : "=r"(a[0]), "=r"(a[1]), "=r"(a[2]), "=r"(a[3]) : "r"(addr));
            }
            unsigned b[2][4];
#pragma unroll
            for (int t16 = 0; t16 < 2; t16++) {
                unsigned addr = smaddr(Ws + (k0 + (lane & 15)) * WPAD + ngc + t16 * 16 + 8 * (lane >> 4));
                asm volatile("ldmatrix.sync.aligned.m8n8.x4.trans.shared.b16 {%0,%1,%2,%3}, [%4];\n"
                             : "=r"(b[t16][0]), "=r"(b[t16][1]), "=r"(b[t16][2]), "=r"(b[t16][3])
                             : "r"(addr));
            }
#pragma unroll
            for (int nt = 0; nt < 4; nt++) {
                unsigned b0 = b[nt >> 1][(nt & 1) * 2];
                unsigned b1 = b[nt >> 1][(nt & 1) * 2 + 1];
                asm volatile(
                    "mma.sync.aligned.m16n8k16.row.col.f32.bf16.bf16.f32 "
                    "{%0,%1,%2,%3}, {%4,%5,%6,%7}, {%8,%9}, {%0,%1,%2,%3};\n"
                    : "+f"(acc[nt][0]), "+f"(acc[nt][1]), "+f"(acc[nt][2]), "+f"(acc[nt][3])
                    : "r"(a[0]), "r"(a[1]), "r"(a[2]), "r"(a[3]), "r"(b0), "r"(b1));
            }
        }

        // reduce k-halves: odd (kh=1) warps store, even warps add
        int r = lane >> 2;
        int cbase = ngc + (lane & 3) * 2;
        if (kh) {
#pragma unroll
            for (int nt = 0; nt < 4; nt++) {
                *(float2*)(gates + r * 128 + cbase + nt * 8)       = make_float2(acc[nt][0], acc[nt][1]);
                *(float2*)(gates + (r + 8) * 128 + cbase + nt * 8) = make_float2(acc[nt][2], acc[nt][3]);
            }
        }
        __syncthreads();
        if (!kh) {
#pragma unroll
            for (int nt = 0; nt < 4; nt++) {
                float2* p0 = (float2*)(gates + r * 128 + cbase + nt * 8);
                float2* p1 = (float2*)(gates + (r + 8) * 128 + cbase + nt * 8);
                float2 v0 = *p0, v1 = *p1;
                v0.x += acc[nt][0]; v0.y += acc[nt][1];
                v1.x += acc[nt][2]; v1.y += acc[nt][3];
                *p0 = v0; *p1 = v1;
            }
        }
        __syncthreads();

        // gate math: thread -> (gb, jp), (gb, jp+1)
        {
            float2 gi = *(float2*)(gates + gb * 128 + jp);
            float2 gf = *(float2*)(gates + gb * 128 + 32 + jp);
            float2 gg = *(float2*)(gates + gb * 128 + 64 + jp);
            float2 go = *(float2*)(gates + gb * 128 + 96 + jp);
            gi.x += xq0.x; gi.y += xq0.y;
            gf.x += xq1.x; gf.y += xq1.y;
            gg.x += xq2.x; gg.y += xq2.y;
            go.x += xq3.x; go.y += xq3.y;
            float2 c = *(float2*)(csm + gb * 32 + jp);
            float si0 = 1.f / (1.f + __expf(-gi.x)), si1 = 1.f / (1.f + __expf(-gi.y));
            float sf0 = 1.f / (1.f + __expf(-gf.x)), sf1 = 1.f / (1.f + __expf(-gf.y));
            float so0 = 1.f / (1.f + __expf(-go.x)), so1 = 1.f / (1.f + __expf(-go.y));
            c.x = sf0 * c.x + si0 * tanhf(gg.x);
            c.y = sf1 * c.y + si1 * tanhf(gg.y);
            *(float2*)(csm + gb * 32 + jp) = c;
            float h0 = so0 * tanhf(c.x);
            float h1 = so1 * tanhf(c.y);
            // publish bf16 to exchange (parity of next step)
            __nv_bfloat162 hp = __floats2bfloat162_rn(h0, h1);
            unsigned* dst = (unsigned*)(&g_hex[dir][bg][(s + 1) & 1][gb * HH + j0 + jp]);
            __stcg(dst, *(unsigned*)&hp);
            // store fp32 h for tag projection
            *(float2*)(hs + ((size_t)t * BB + bg * 16 + gb) * HH + j0 + jp) = make_float2(h0, h1);
        }

        asm volatile("barrier.cluster.arrive.aligned;\n" ::: "memory");
        asm volatile("barrier.cluster.wait.aligned;\n" ::: "memory");
    }
}

// ------------------------- tag projection -------------------------
__global__ __launch_bounds__(256) void k_tag(const float* __restrict__ Wtag,
                                             const float* __restrict__ btag)
{
    extern __shared__ float sm[];
    float* Wt = sm;                 // [30][1024] (transposed)
    float* hh = Wt + KK * 1024;     // [1024]
    int tid = threadIdx.x;
    for (int idx = tid; idx < 1024 * KK; idx += 256) {
        int d = idx / KK;
        int k = idx - d * KK;
        Wt[k * 1024 + d] = Wtag[idx];
    }
    __syncthreads();
    int w = tid >> 5, lane = tid & 31;
    for (int m = blockIdx.x; m < MTOT; m += gridDim.x) {
        int t = m >> 5, b = m & 31;
        {
            int hidx = tid;
            const float* src = (hidx < 128)
                ? (g_hs[0] + ((size_t)t * BB + b) * HH + hidx * 4)
                : (g_hs[1] + ((size_t)t * BB + b) * HH + (hidx - 128) * 4);
            *(float4*)(&hh[hidx * 4]) = *(const float4*)src;
        }
        __syncthreads();
#pragma unroll
        for (int q = 0; q < 4; q++) {
            int k = w + q * 8;
            if (k < KK) {
                const float* wr = Wt + k * 1024;
                float s = 0.f;
#pragma unroll
                for (int i = 0; i < 8; i++) {
                    int d = lane * 4 + i * 128;
                    float4 hv = *(const float4*)(&hh[d]);
                    float4 wv = *(const float4*)(&wr[d]);
                    s += hv.x * wv.x + hv.y * wv.y + hv.z * wv.z + hv.w * wv.w;
                }
#pragma unroll
                for (int off = 16; off; off >>= 1)
                    s += __shfl_down_sync(0xffffffffu, s, off);
                if (lane == 0)
                    g_feats[((size_t)b * TT + t) * KK + k] = s + btag[k];
            }
        }
        __syncthreads();
    }
}

// ------------------------- CRF NLL (one warp per sentence) -------------------------
__global__ void k_crf(const float* __restrict__ trans, const int* __restrict__ tags,
                      float* __restrict__ out)
{
    int b = blockIdx.x;
    int lane = threadIdx.x;
    float trow[KK];
    int lr = (lane < KK) ? lane : 0;
#pragma unroll
    for (int p = 0; p < KK; p++) trow[p] = trans[lr * KK + p];
    float alpha = (lane == TSTART) ? 0.f : NEGV;
    const float* fb = g_feats + (size_t)b * TT * KK;
    for (int t = 0; t < TT; t++) {
        float emit = (lane < KK) ? fb[t * KK + lane] : 0.f;
        float v[KK];
        float vmax = -1e30f;
#pragma unroll
        for (int p = 0; p < KK; p++) {
            v[p] = __shfl_sync(0xffffffffu, alpha, p) + trow[p];
            vmax = fmaxf(vmax, v[p]);
        }
        float ssum = 0.f;
#pragma unroll
        for (int p = 0; p < KK; p++) ssum += __expf(v[p] - vmax);
        float na = vmax + __logf(ssum) + emit;
        alpha = (lane < KK) ? na : NEGV;
    }
    float v = (lane < KK) ? (alpha + trans[TSTOP * KK + lane]) : -1e30f;
    float m = v;
#pragma unroll
    for (int off = 16; off; off >>= 1) m = fmaxf(m, __shfl_xor_sync(0xffffffffu, m, off));
    float e = (lane < KK) ? __expf(v - m) : 0.f;
#pragma unroll
    for (int off = 16; off; off >>= 1) e += __shfl_xor_sync(0xffffffffu, e, off);
    float logz = m + __logf(e);
    const int* tg = tags + b * TT;
    float gold = 0.f;
    for (int j = lane; j < TT + 1; j += 32) {
        int prev = (j == 0) ? TSTART : tg[j - 1];
        int nxt  = (j < TT) ? tg[j] : TSTOP;
        gold += trans[nxt * KK + prev];
        if (j < TT) gold += fb[j * KK + tg[j]];
    }
#pragma unroll
    for (int off = 16; off; off >>= 1) gold += __shfl_xor_sync(0xffffffffu, gold, off);
    if (lane == 0) out[b] = logz - gold;
}

// ------------------------- launcher -------------------------
extern "C" void kernel_launch(void* const* d_in, const int* in_sizes, int n_in,
                              void* d_out, int out_size)
{
    const int*   ids   = (const int*)  d_in[0];
    const int*   tags  = (const int*)  d_in[1];
    const float* embed = (const float*)d_in[2];
    const float* Wihf  = (const float*)d_in[3];
    const float* Whhf  = (const float*)d_in[4];
    const float* bf    = (const float*)d_in[5];
    const float* Wihb  = (const float*)d_in[6];
    const float* Whhb  = (const float*)d_in[7];
    const float* bb    = (const float*)d_in[8];
    const float* Wtag  = (const float*)d_in[9];
    const float* btag  = (const float*)d_in[10];
    const float* trans = (const float*)d_in[11];
    float* out = (float*)d_out;

    size_t tsm = (size_t)(KK * 1024 + 1024) * sizeof(float);
    cudaFuncSetAttribute(k_tag, cudaFuncAttributeMaxDynamicSharedMemorySize, (int)tsm);
    cudaFuncSetAttribute(k_lstm2, cudaFuncAttributeMaxDynamicSharedMemorySize, LSM_BYTES);
    cudaFuncSetAttribute(k_lstm2, cudaFuncAttributeNonPortableClusterSizeAllowed, 1);

    __nv_bfloat16* wb0; cudaGetSymbolAddress((void**)&wb0, g_wb);
    __nv_bfloat16* wb2; cudaGetSymbolAddress((void**)&wb2, g_wb2);

    {
        size_t nx = (size_t)MTOT * (DIN / 4);
        k_castx<<<(unsigned)((nx + 255) / 256), 256>>>(embed, ids);
        size_t nw = (size_t)DIN * G4 / 4;
        k_cast<<<(unsigned)((nw + 255) / 256), 256>>>(Wihf, wb0, nw);
        k_cast<<<(unsigned)((nw + 255) / 256), 256>>>(Wihb, wb0 + (size_t)DIN * G4, nw);
        size_t nh = (size_t)HH * G4 / 4;
        k_cast<<<(unsigned)((nh + 255) / 256), 256>>>(Whhf, wb2, nh);
        k_cast<<<(unsigned)((nh + 255) / 256), 256>>>(Whhb, wb2 + (size_t)HH * G4, nh);
    }

    dim3 gg(G4 / BN, MTOT / BM);
    k_gemm<<<gg, 256>>>(bf, 0);
    k_gemm<<<gg, 256>>>(bb, 1);
    k_lstm2<<<64, 256, LSM_BYTES>>>();
    k_tag<<<148, 256, tsm>>>(Wtag, btag);
    k_crf<<<BB, 32>>>(trans, tags, out);
}

// round 4
// speedup vs baseline: 4.3516x; 1.1505x over previous
#include <cuda_runtime.h>
#include <cuda_bf16.h>
#include <math.h>

#define BB 32
#define TT 512
#define DIN 1824
#define HH 512
#define G4 2048
#define KK 30
#define TSTART 28
#define TSTOP 29
#define NEGV (-10000.0f)
#define MTOT (TT*BB)            /* 16384 */

// ------------------------- device scratch -------------------------
__device__ float g_xw[2][(size_t)MTOT*G4];      // [dir][m][4H], m = t*B+b
__device__ float g_hs[2][(size_t)MTOT*HH];      // hf/hb, [t][b][d]
__device__ float g_feats[(size_t)BB*TT*KK];     // [b][t][k]
__device__ __nv_bfloat16 g_xb[(size_t)MTOT*DIN];     // gathered embeddings, bf16
__device__ __nv_bfloat16 g_wb[2][(size_t)DIN*G4];    // W_ih f/b, bf16
__device__ __nv_bfloat16 g_wb2[2][(size_t)HH*G4];    // W_hh f/b, bf16
__device__ __nv_bfloat16 g_hex[2][2][2][16*HH];      // [dir][bgrp][parity][b][k]

__device__ __forceinline__ unsigned smaddr(const void* p)
{
    return (unsigned)__cvta_generic_to_shared(p);
}

// ------------------------- cast kernels -------------------------
__global__ __launch_bounds__(256) void k_castx(const float* __restrict__ embed,
                                               const int* __restrict__ ids)
{
    size_t idx = (size_t)blockIdx.x * 256 + threadIdx.x;
    if (idx >= (size_t)MTOT * (DIN / 4)) return;
    int m = (int)(idx / (DIN / 4));
    int q = (int)(idx % (DIN / 4));
    int id = ids[(m & 31) * TT + (m >> 5)];
    float4 v = *(const float4*)(embed + (size_t)id * DIN + 4 * q);
    __nv_bfloat162 lo = __floats2bfloat162_rn(v.x, v.y);
    __nv_bfloat162 hi = __floats2bfloat162_rn(v.z, v.w);
    uint2 pk; pk.x = *(unsigned*)&lo; pk.y = *(unsigned*)&hi;
    *(uint2*)(g_xb + (size_t)m * DIN + 4 * q) = pk;
}

#define NW4 ((size_t)DIN*G4/4)
#define NH4 ((size_t)HH*G4/4)

__global__ __launch_bounds__(256) void k_castw(const float* __restrict__ f0,
                                               const float* __restrict__ f1,
                                               const float* __restrict__ f2,
                                               const float* __restrict__ f3)
{
    size_t idx = (size_t)blockIdx.x * 256 + threadIdx.x;
    const float* src; __nv_bfloat16* dst;
    if (idx < NW4)                    { src = f0; dst = g_wb[0]; }
    else if (idx < 2 * NW4)           { src = f1; dst = g_wb[1]; idx -= NW4; }
    else if (idx < 2 * NW4 + NH4)     { src = f2; dst = g_wb2[0]; idx -= 2 * NW4; }
    else if (idx < 2 * NW4 + 2 * NH4) { src = f3; dst = g_wb2[1]; idx -= 2 * NW4 + NH4; }
    else return;
    float4 v = *(const float4*)(src + 4 * idx);
    __nv_bfloat162 lo = __floats2bfloat162_rn(v.x, v.y);
    __nv_bfloat162 hi = __floats2bfloat162_rn(v.z, v.w);
    uint2 pk; pk.x = *(unsigned*)&lo; pk.y = *(unsigned*)&hi;
    *(uint2*)(dst + 4 * idx) = pk;
}

__global__ __launch_bounds__(256) void k_zero(void)
{
    // zero g_hex: 2*2*2*16*512 bf16 = 131072 B = 8192 uint4
    unsigned idx = blockIdx.x * 256 + threadIdx.x;
    if (idx < 8192) ((uint4*)g_hex)[idx] = make_uint4(0, 0, 0, 0);
}

// ------------------------- bf16 tensor-core input GEMM -------------------------
#define BM 128
#define BN 128
#define BK 32
#define APAD 8
#define BPAD 8
#define NKT (DIN / BK)   /* 57 */

__global__ __launch_bounds__(256) void k_gemm(const float* __restrict__ bias, int dir)
{
    __shared__ __nv_bfloat16 As[2][BM][BK + APAD];
    __shared__ __nv_bfloat16 Bs[2][BK][BN + BPAD];

    const __nv_bfloat16* A = g_xb;
    const __nv_bfloat16* Bw = g_wb[dir];
    float* out = g_xw[dir];

    int tid = threadIdx.x;
    int wid = tid >> 5;
    int lane = tid & 31;
    int m0 = blockIdx.y * BM;
    int n0 = blockIdx.x * BN;
    int wm = (wid & 3) * 32;
    int wn = (wid >> 2) * 64;

    float acc[2][8][4];
#pragma unroll
    for (int i = 0; i < 2; i++)
#pragma unroll
        for (int j = 0; j < 8; j++)
#pragma unroll
            for (int r = 0; r < 4; r++) acc[i][j][r] = 0.f;

    auto loadA = [&](int buf, int k0) {
#pragma unroll
        for (int j = 0; j < 2; j++) {
            int c = tid + j * 256;
            int r = c >> 2, q = c & 3;
            unsigned dst = smaddr(&As[buf][r][q * 8]);
            const __nv_bfloat16* src = A + (size_t)(m0 + r) * DIN + k0 + q * 8;
            asm volatile("cp.async.cg.shared.global [%0], [%1], 16;\n" :: "r"(dst), "l"(src));
        }
    };
    auto loadB = [&](int buf, int k0) {
#pragma unroll
        for (int j = 0; j < 2; j++) {
            int c = tid + j * 256;
            int r = c >> 4, q = c & 15;
            unsigned dst = smaddr(&Bs[buf][r][q * 8]);
            const __nv_bfloat16* src = Bw + (size_t)(k0 + r) * G4 + n0 + q * 8;
            asm volatile("cp.async.cg.shared.global [%0], [%1], 16;\n" :: "r"(dst), "l"(src));
        }
    };

    loadA(0, 0); loadB(0, 0);
    asm volatile("cp.async.commit_group;\n");

    for (int kt = 0; kt < NKT; kt++) {
        int buf = kt & 1;
        if (kt + 1 < NKT) {
            loadA(buf ^ 1, (kt + 1) * BK);
            loadB(buf ^ 1, (kt + 1) * BK);
            asm volatile("cp.async.commit_group;\n");
            asm volatile("cp.async.wait_group 1;\n");
        } else {
            asm volatile("cp.async.wait_group 0;\n");
        }
        __syncthreads();

#pragma unroll
        for (int ks = 0; ks < 2; ks++) {
            int k0 = ks * 16;
            unsigned a[2][4];
#pragma unroll
            for (int mi = 0; mi < 2; mi++) {
                unsigned addr = smaddr(&As[buf][wm + mi * 16 + (lane & 15)][k0 + 8 * (lane >> 4)]);
                asm volatile("ldmatrix.sync.aligned.m8n8.x4.shared.b16 {%0,%1,%2,%3}, [%4];\n"
                             : "=r"(a[mi][0]), "=r"(a[mi][1]), "=r"(a[mi][2]), "=r"(a[mi][3])
                             : "r"(addr));
            }
            unsigned b[4][4];
#pragma unroll
            for (int nj = 0; nj < 4; nj++) {
                unsigned addr = smaddr(&Bs[buf][k0 + (lane & 15)][wn + nj * 16 + 8 * (lane >> 4)]);
                asm volatile("ldmatrix.sync.aligned.m8n8.x4.trans.shared.b16 {%0,%1,%2,%3}, [%4];\n"
                             : "=r"(b[nj][0]), "=r"(b[nj][1]), "=r"(b[nj][2]), "=r"(b[nj][3])
                             : "r"(addr));
            }
#pragma unroll
            for (int mi = 0; mi < 2; mi++)
#pragma unroll
                for (int ni = 0; ni < 8; ni++) {
                    unsigned b0 = b[ni >> 1][(ni & 1) * 2];
                    unsigned b1 = b[ni >> 1][(ni & 1) * 2 + 1];
                    asm volatile(
                        "mma.sync.aligned.m16n8k16.row.col.f32.bf16.bf16.f32 "
                        "{%0,%1,%2,%3}, {%4,%5,%6,%7}, {%8,%9}, {%0,%1,%2,%3};\n"
                        : "+f"(acc[mi][ni][0]), "+f"(acc[mi][ni][1]),
                          "+f"(acc[mi][ni][2]), "+f"(acc[mi][ni][3])
                        : "r"(a[mi][0]), "r"(a[mi][1]), "r"(a[mi][2]), "r"(a[mi][3]),
                          "r"(b0), "r"(b1));
                }
        }
        __syncthreads();
    }

#pragma unroll
    for (int mi = 0; mi < 2; mi++) {
#pragma unroll
        for (int ni = 0; ni < 8; ni++) {
            int col = n0 + wn + ni * 8 + (lane & 3) * 2;
            float bx = bias[col], by = bias[col + 1];
            int row0 = m0 + wm + mi * 16 + (lane >> 2);
            float2 v0 = make_float2(acc[mi][ni][0] + bx, acc[mi][ni][1] + by);
            float2 v1 = make_float2(acc[mi][ni][2] + bx, acc[mi][ni][3] + by);
            *(float2*)(out + (size_t)row0 * G4 + col) = v0;
            *(float2*)(out + (size_t)(row0 + 8) * G4 + col) = v1;
        }
    }
}

// ------------------------- LSTM recurrence: 4 clusters of 16 CTAs -------------------------
// 512 threads/CTA, 16 warps: kh = wid&1 (k half of 256), ng = wid>>1 (16 n-cols).
// B fragments (W_hh slice) hoisted into registers ONCE (64 regs/warp); inner loop
// per step is 16 ldmatrix(A) + 32 mma per warp. h exchanged via L2 (stcg publish,
// cp.async pull), cluster barrier per step.
#define WPAD 136            /* 128 + 8 bf16 pad */
#define SPAD 520            /* 512 + 8 bf16 pad */
#define GPAD 136            /* gates row stride in floats */
#define LSM_BYTES  (512*WPAD*2 + 16*SPAD*2 + 16*GPAD*4 + 512*4)

__global__ __launch_bounds__(512, 1) __cluster_dims__(16, 1, 1)
void k_lstm2(void)
{
    extern __shared__ char smraw[];
    __nv_bfloat16* Ws   = (__nv_bfloat16*)smraw;                       // [512][136]
    __nv_bfloat16* Astg = Ws + 512 * WPAD;                             // [16][520]
    float*         gates = (float*)(Astg + 16 * SPAD);                 // [16][136]
    float*         csm   = gates + 16 * GPAD;                          // [16][32]

    int tid = threadIdx.x;
    int wid = tid >> 5;
    int lane = tid & 31;
    int cid = blockIdx.x >> 4;
    int rank = blockIdx.x & 15;
    int dir = cid >> 1;
    int bg  = cid & 1;
    int j0  = rank * 32;

    const __nv_bfloat16* Whh = g_wb2[dir];
    const float* xw = g_xw[dir];
    float* hs = g_hs[dir];

    // load W slice: cols {q*512 + j0 + j : q<4, j<32} -> Ws[k][q*32+j]
    for (int c = tid; c < 512 * 16; c += 512) {
        int k = c >> 4, ch = c & 15;
        int q = ch >> 2, jb = (ch & 3) * 8;
        uint4 v = *(const uint4*)(Whh + (size_t)k * G4 + q * 512 + j0 + jb);
        *(uint4*)(Ws + k * WPAD + q * 32 + jb) = v;
    }
    // zero staging (h0 = 0) and c
    for (int c = tid; c < 16 * SPAD / 4; c += 512) ((uint2*)Astg)[c] = make_uint2(0, 0);
    csm[tid] = 0.f;
    __syncthreads();

    int kh = wid & 1;
    int ng = wid >> 1;          // 0..7
    int kbase = kh * 256;
    int ngc = ng * 16;

    // hoist B fragments: 16 k16-tiles x (2 n8-tiles -> 4 regs)
    unsigned bfr[16][4];
#pragma unroll
    for (int kk = 0; kk < 16; kk++) {
        int k0 = kbase + kk * 16;
        unsigned addr = smaddr(Ws + (k0 + (lane & 15)) * WPAD + ngc + 8 * (lane >> 4));
        asm volatile("ldmatrix.sync.aligned.m8n8.x4.trans.shared.b16 {%0,%1,%2,%3}, [%4];\n"
                     : "=r"(bfr[kk][0]), "=r"(bfr[kk][1]), "=r"(bfr[kk][2]), "=r"(bfr[kk][3])
                     : "r"(addr));
    }

    int gb = wid;               // gate-math batch (0..15)
    int gj = lane;              // gate-math h-dim (0..31)

    for (int s = 0; s < TT; s++) {
        int t = dir ? (TT - 1 - s) : s;
        if (s) {
            const __nv_bfloat16* hx = g_hex[dir][bg][s & 1];
#pragma unroll
            for (int i = 0; i < 2; i++) {
                int c = tid + i * 512;
                int row = c >> 6, cq = c & 63;
                unsigned dst = smaddr(Astg + row * SPAD + cq * 8);
                const __nv_bfloat16* src = hx + row * HH + cq * 8;
                asm volatile("cp.async.cg.shared.global [%0], [%1], 16;\n" :: "r"(dst), "l"(src));
            }
            asm volatile("cp.async.commit_group;\n");
        }
        // prefetch xw for gate math
        const float* xrow = xw + (size_t)(t * BB + bg * 16 + gb) * G4 + j0 + gj;
        float xq0 = xrow[0];
        float xq1 = xrow[512];
        float xq2 = xrow[1024];
        float xq3 = xrow[1536];

        asm volatile("cp.async.wait_group 0;\n");
        __syncthreads();

        // mma: M=16 (batches), N=16 (ng), K=256 (kh)
        float acc[2][4];
#pragma unroll
        for (int i = 0; i < 2; i++)
#pragma unroll
            for (int j = 0; j < 4; j++) acc[i][j] = 0.f;

#pragma unroll
        for (int kk = 0; kk < 16; kk++) {
            int k0 = kbase + kk * 16;
            unsigned a[4];
            unsigned addr = smaddr(Astg + (lane & 15) * SPAD + k0 + 8 * (lane >> 4));
            asm volatile("ldmatrix.sync.aligned.m8n8.x4.shared.b16 {%0,%1,%2,%3}, [%4];\n"
                         : "=r"(a[0]), "=r"(a[1]), "=r"(a[2]), "=r"(a[3]) : "r"(addr));
#pragma unroll
            for (int nt = 0; nt < 2; nt++) {
                asm volatile(
                    "mma.sync.aligned.m16n8k16.row.col.f32.bf16.bf16.f32 "
                    "{%0,%1,%2,%3}, {%4,%5,%6,%7}, {%8,%9}, {%0,%1,%2,%3};\n"
                    : "+f"(acc[nt][0]), "+f"(acc[nt][1]), "+f"(acc[nt][2]), "+f"(acc[nt][3])
                    : "r"(a[0]), "r"(a[1]), "r"(a[2]), "r"(a[3]),
                      "r"(bfr[kk][nt * 2]), "r"(bfr[kk][nt * 2 + 1]));
            }
        }

        // reduce k-halves
        int r = lane >> 2;
        int cbase = ngc + (lane & 3) * 2;
        if (kh) {
#pragma unroll
            for (int nt = 0; nt < 2; nt++) {
                *(float2*)(gates + r * GPAD + cbase + nt * 8)       = make_float2(acc[nt][0], acc[nt][1]);
                *(float2*)(gates + (r + 8) * GPAD + cbase + nt * 8) = make_float2(acc[nt][2], acc[nt][3]);
            }
        }
        __syncthreads();
        if (!kh) {
#pragma unroll
            for (int nt = 0; nt < 2; nt++) {
                float2* p0 = (float2*)(gates + r * GPAD + cbase + nt * 8);
                float2* p1 = (float2*)(gates + (r + 8) * GPAD + cbase + nt * 8);
                float2 v0 = *p0, v1 = *p1;
                v0.x += acc[nt][0]; v0.y += acc[nt][1];
                v1.x += acc[nt][2]; v1.y += acc[nt][3];
                *p0 = v0; *p1 = v1;
            }
        }
        __syncthreads();

        // gate math: thread -> (gb, gj)
        {
            float gi = gates[gb * GPAD + gj]       + xq0;
            float gf = gates[gb * GPAD + 32 + gj]  + xq1;
            float gg = gates[gb * GPAD + 64 + gj]  + xq2;
            float go = gates[gb * GPAD + 96 + gj]  + xq3;
            float c  = csm[gb * 32 + gj];
            float si = 1.f / (1.f + __expf(-gi));
            float sf = 1.f / (1.f + __expf(-gf));
            float so = 1.f / (1.f + __expf(-go));
            c = sf * c + si * tanhf(gg);
            csm[gb * 32 + gj] = c;
            float h = so * tanhf(c);
            __nv_bfloat16 hb = __float2bfloat16(h);
            unsigned short hraw = *(unsigned short*)&hb;
            __nv_bfloat16* dst = &g_hex[dir][bg][(s + 1) & 1][gb * HH + j0 + gj];
            asm volatile("st.global.cg.b16 [%0], %1;\n" :: "l"(dst), "h"(hraw));
            hs[((size_t)t * BB + bg * 16 + gb) * HH + j0 + gj] = h;
        }

        asm volatile("barrier.cluster.arrive.aligned;\n" ::: "memory");
        asm volatile("barrier.cluster.wait.aligned;\n" ::: "memory");
    }
}

// ------------------------- tag projection -------------------------
__global__ __launch_bounds__(256) void k_tag(const float* __restrict__ Wtag,
                                             const float* __restrict__ btag)
{
    extern __shared__ float sm[];
    float* Wt = sm;                 // [30][1024] (transposed)
    float* hh = Wt + KK * 1024;     // [1024]
    int tid = threadIdx.x;
    for (int idx = tid; idx < 1024 * KK; idx += 256) {
        int d = idx / KK;
        int k = idx - d * KK;
        Wt[k * 1024 + d] = Wtag[idx];
    }
    __syncthreads();
    int w = tid >> 5, lane = tid & 31;
    for (int m = blockIdx.x; m < MTOT; m += gridDim.x) {
        int t = m >> 5, b = m & 31;
        {
            int hidx = tid;
            const float* src = (hidx < 128)
                ? (g_hs[0] + ((size_t)t * BB + b) * HH + hidx * 4)
                : (g_hs[1] + ((size_t)t * BB + b) * HH + (hidx - 128) * 4);
            *(float4*)(&hh[hidx * 4]) = *(const float4*)src;
        }
        __syncthreads();
#pragma unroll
        for (int q = 0; q < 4; q++) {
            int k = w + q * 8;
            if (k < KK) {
                const float* wr = Wt + k * 1024;
                float s = 0.f;
#pragma unroll
                for (int i = 0; i < 8; i++) {
                    int d = lane * 4 + i * 128;
                    float4 hv = *(const float4*)(&hh[d]);
                    float4 wv = *(const float4*)(&wr[d]);
                    s += hv.x * wv.x + hv.y * wv.y + hv.z * wv.z + hv.w * wv.w;
                }
#pragma unroll
                for (int off = 16; off; off >>= 1)
                    s += __shfl_down_sync(0xffffffffu, s, off);
                if (lane == 0)
                    g_feats[((size_t)b * TT + t) * KK + k] = s + btag[k];
            }
        }
        __syncthreads();
    }
}

// ------------------------- CRF NLL (one warp per sentence) -------------------------
__global__ void k_crf(const float* __restrict__ trans, const int* __restrict__ tags,
                      float* __restrict__ out)
{
    int b = blockIdx.x;
    int lane = threadIdx.x;
    float trow[KK];
    int lr = (lane < KK) ? lane : 0;
#pragma unroll
    for (int p = 0; p < KK; p++) trow[p] = trans[lr * KK + p];
    float alpha = (lane == TSTART) ? 0.f : NEGV;
    const float* fb = g_feats + (size_t)b * TT * KK;
    for (int t = 0; t < TT; t++) {
        float emit = (lane < KK) ? fb[t * KK + lane] : 0.f;
        float v[KK];
        float vmax = -1e30f;
#pragma unroll
        for (int p = 0; p < KK; p++) {
            v[p] = __shfl_sync(0xffffffffu, alpha, p) + trow[p];
            vmax = fmaxf(vmax, v[p]);
        }
        float ssum = 0.f;
#pragma unroll
        for (int p = 0; p < KK; p++) ssum += __expf(v[p] - vmax);
        float na = vmax + __logf(ssum) + emit;
        alpha = (lane < KK) ? na : NEGV;
    }
    float v = (lane < KK) ? (alpha + trans[TSTOP * KK + lane]) : -1e30f;
    float m = v;
#pragma unroll
    for (int off = 16; off; off >>= 1) m = fmaxf(m, __shfl_xor_sync(0xffffffffu, m, off));
    float e = (lane < KK) ? __expf(v - m) : 0.f;
#pragma unroll
    for (int off = 16; off; off >>= 1) e += __shfl_xor_sync(0xffffffffu, e, off);
    float logz = m + __logf(e);
    const int* tg = tags + b * TT;
    float gold = 0.f;
    for (int j = lane; j < TT + 1; j += 32) {
        int prev = (j == 0) ? TSTART : tg[j - 1];
        int nxt  = (j < TT) ? tg[j] : TSTOP;
        gold += trans[nxt * KK + prev];
        if (j < TT) gold += fb[j * KK + tg[j]];
    }
#pragma unroll
    for (int off = 16; off; off >>= 1) gold += __shfl_xor_sync(0xffffffffu, gold, off);
    if (lane == 0) out[b] = logz - gold;
}

// ------------------------- launcher -------------------------
extern "C" void kernel_launch(void* const* d_in, const int* in_sizes, int n_in,
                              void* d_out, int out_size)
{
    const int*   ids   = (const int*)  d_in[0];
    const int*   tags  = (const int*)  d_in[1];
    const float* embed = (const float*)d_in[2];
    const float* Wihf  = (const float*)d_in[3];
    const float* Whhf  = (const float*)d_in[4];
    const float* bf    = (const float*)d_in[5];
    const float* Wihb  = (const float*)d_in[6];
    const float* Whhb  = (const float*)d_in[7];
    const float* bb    = (const float*)d_in[8];
    const float* Wtag  = (const float*)d_in[9];
    const float* btag  = (const float*)d_in[10];
    const float* trans = (const float*)d_in[11];
    float* out = (float*)d_out;

    size_t tsm = (size_t)(KK * 1024 + 1024) * sizeof(float);
    cudaFuncSetAttribute(k_tag, cudaFuncAttributeMaxDynamicSharedMemorySize, (int)tsm);
    cudaFuncSetAttribute(k_lstm2, cudaFuncAttributeMaxDynamicSharedMemorySize, LSM_BYTES);
    cudaFuncSetAttribute(k_lstm2, cudaFuncAttributeNonPortableClusterSizeAllowed, 1);

    // launch order chosen so ncu (-s 5 -c 1) profiles k_lstm2
    {
        size_t nx = (size_t)MTOT * (DIN / 4);
        k_castx<<<(unsigned)((nx + 255) / 256), 256>>>(embed, ids);            // 0
        size_t nwt = 2 * NW4 + 2 * NH4;
        k_castw<<<(unsigned)((nwt + 255) / 256), 256>>>(Wihf, Wihb, Whhf, Whhb); // 1
    }
    dim3 gg(G4 / BN, MTOT / BM);
    k_gemm<<<gg, 256>>>(bf, 0);                                                // 2
    k_gemm<<<gg, 256>>>(bb, 1);                                                // 3
    k_zero<<<32, 256>>>();                                                     // 4
    k_lstm2<<<64, 512, LSM_BYTES>>>();                                         // 5  <- ncu
    k_tag<<<148, 256, tsm>>>(Wtag, btag);                                      // 6
    k_crf<<<BB, 32>>>(trans, tags, out);                                       // 7
}

// round 5
// speedup vs baseline: 4.6938x; 1.0786x over previous
#include <cuda_runtime.h>
#include <cuda_bf16.h>
#include <math.h>

#define BB 32
#define TT 512
#define DIN 1824
#define HH 512
#define G4 2048
#define KK 30
#define TSTART 28
#define TSTOP 29
#define NEGV (-10000.0f)
#define MTOT (TT*BB)            /* 16384 */

// ------------------------- device scratch -------------------------
__device__ float g_xw[2][(size_t)MTOT*G4];      // [dir][m][4H], m = t*B+b
__device__ float g_hs[2][(size_t)MTOT*HH];      // hf/hb, [t][b][d]
__device__ float g_feats[(size_t)BB*TT*KK];     // [b][t][k]
__device__ __nv_bfloat16 g_xb[(size_t)MTOT*DIN];     // gathered embeddings, bf16
__device__ __nv_bfloat16 g_wb[2][(size_t)DIN*G4];    // W_ih f/b, bf16
__device__ __nv_bfloat16 g_wb2[2][(size_t)HH*G4];    // W_hh f/b, bf16
__device__ __nv_bfloat16 g_hex[2][2][2][16*HH];      // (legacy, only zeroed)

__device__ __forceinline__ unsigned smaddr(const void* p)
{
    return (unsigned)__cvta_generic_to_shared(p);
}

__device__ __forceinline__ float tanha(float x)
{
    float r;
    asm("tanh.approx.f32 %0, %1;" : "=f"(r) : "f"(x));
    return r;
}

// ------------------------- cast kernels -------------------------
__global__ __launch_bounds__(256) void k_castx(const float* __restrict__ embed,
                                               const int* __restrict__ ids)
{
    size_t idx = (size_t)blockIdx.x * 256 + threadIdx.x;
    if (idx >= (size_t)MTOT * (DIN / 4)) return;
    int m = (int)(idx / (DIN / 4));
    int q = (int)(idx % (DIN / 4));
    int id = ids[(m & 31) * TT + (m >> 5)];
    float4 v = *(const float4*)(embed + (size_t)id * DIN + 4 * q);
    __nv_bfloat162 lo = __floats2bfloat162_rn(v.x, v.y);
    __nv_bfloat162 hi = __floats2bfloat162_rn(v.z, v.w);
    uint2 pk; pk.x = *(unsigned*)&lo; pk.y = *(unsigned*)&hi;
    *(uint2*)(g_xb + (size_t)m * DIN + 4 * q) = pk;
}

#define NW4 ((size_t)DIN*G4/4)
#define NH4 ((size_t)HH*G4/4)

__global__ __launch_bounds__(256) void k_castw(const float* __restrict__ f0,
                                               const float* __restrict__ f1,
                                               const float* __restrict__ f2,
                                               const float* __restrict__ f3)
{
    size_t idx = (size_t)blockIdx.x * 256 + threadIdx.x;
    const float* src; __nv_bfloat16* dst;
    if (idx < NW4)                    { src = f0; dst = g_wb[0]; }
    else if (idx < 2 * NW4)           { src = f1; dst = g_wb[1]; idx -= NW4; }
    else if (idx < 2 * NW4 + NH4)     { src = f2; dst = g_wb2[0]; idx -= 2 * NW4; }
    else if (idx < 2 * NW4 + 2 * NH4) { src = f3; dst = g_wb2[1]; idx -= 2 * NW4 + NH4; }
    else return;
    float4 v = *(const float4*)(src + 4 * idx);
    __nv_bfloat162 lo = __floats2bfloat162_rn(v.x, v.y);
    __nv_bfloat162 hi = __floats2bfloat162_rn(v.z, v.w);
    uint2 pk; pk.x = *(unsigned*)&lo; pk.y = *(unsigned*)&hi;
    *(uint2*)(dst + 4 * idx) = pk;
}

__global__ __launch_bounds__(256) void k_zero(void)
{
    unsigned idx = blockIdx.x * 256 + threadIdx.x;
    if (idx < 8192) ((uint4*)g_hex)[idx] = make_uint4(0, 0, 0, 0);
}

// ------------------------- bf16 tensor-core input GEMM -------------------------
#define BM 128
#define BN 128
#define BK 32
#define APAD 8
#define BPAD 8
#define NKT (DIN / BK)   /* 57 */

__global__ __launch_bounds__(256) void k_gemm(const float* __restrict__ bias, int dir)
{
    __shared__ __nv_bfloat16 As[2][BM][BK + APAD];
    __shared__ __nv_bfloat16 Bs[2][BK][BN + BPAD];

    const __nv_bfloat16* A = g_xb;
    const __nv_bfloat16* Bw = g_wb[dir];
    float* out = g_xw[dir];

    int tid = threadIdx.x;
    int wid = tid >> 5;
    int lane = tid & 31;
    int m0 = blockIdx.y * BM;
    int n0 = blockIdx.x * BN;
    int wm = (wid & 3) * 32;
    int wn = (wid >> 2) * 64;

    float acc[2][8][4];
#pragma unroll
    for (int i = 0; i < 2; i++)
#pragma unroll
        for (int j = 0; j < 8; j++)
#pragma unroll
            for (int r = 0; r < 4; r++) acc[i][j][r] = 0.f;

    auto loadA = [&](int buf, int k0) {
#pragma unroll
        for (int j = 0; j < 2; j++) {
            int c = tid + j * 256;
            int r = c >> 2, q = c & 3;
            unsigned dst = smaddr(&As[buf][r][q * 8]);
            const __nv_bfloat16* src = A + (size_t)(m0 + r) * DIN + k0 + q * 8;
            asm volatile("cp.async.cg.shared.global [%0], [%1], 16;\n" :: "r"(dst), "l"(src));
        }
    };
    auto loadB = [&](int buf, int k0) {
#pragma unroll
        for (int j = 0; j < 2; j++) {
            int c = tid + j * 256;
            int r = c >> 4, q = c & 15;
            unsigned dst = smaddr(&Bs[buf][r][q * 8]);
            const __nv_bfloat16* src = Bw + (size_t)(k0 + r) * G4 + n0 + q * 8;
            asm volatile("cp.async.cg.shared.global [%0], [%1], 16;\n" :: "r"(dst), "l"(src));
        }
    };

    loadA(0, 0); loadB(0, 0);
    asm volatile("cp.async.commit_group;\n");

    for (int kt = 0; kt < NKT; kt++) {
        int buf = kt & 1;
        if (kt + 1 < NKT) {
            loadA(buf ^ 1, (kt + 1) * BK);
            loadB(buf ^ 1, (kt + 1) * BK);
            asm volatile("cp.async.commit_group;\n");
            asm volatile("cp.async.wait_group 1;\n");
        } else {
            asm volatile("cp.async.wait_group 0;\n");
        }
        __syncthreads();

#pragma unroll
        for (int ks = 0; ks < 2; ks++) {
            int k0 = ks * 16;
            unsigned a[2][4];
#pragma unroll
            for (int mi = 0; mi < 2; mi++) {
                unsigned addr = smaddr(&As[buf][wm + mi * 16 + (lane & 15)][k0 + 8 * (lane >> 4)]);
                asm volatile("ldmatrix.sync.aligned.m8n8.x4.shared.b16 {%0,%1,%2,%3}, [%4];\n"
                             : "=r"(a[mi][0]), "=r"(a[mi][1]), "=r"(a[mi][2]), "=r"(a[mi][3])
                             : "r"(addr));
            }
            unsigned b[4][4];
#pragma unroll
            for (int nj = 0; nj < 4; nj++) {
                unsigned addr = smaddr(&Bs[buf][k0 + (lane & 15)][wn + nj * 16 + 8 * (lane >> 4)]);
                asm volatile("ldmatrix.sync.aligned.m8n8.x4.trans.shared.b16 {%0,%1,%2,%3}, [%4];\n"
                             : "=r"(b[nj][0]), "=r"(b[nj][1]), "=r"(b[nj][2]), "=r"(b[nj][3])
                             : "r"(addr));
            }
#pragma unroll
            for (int mi = 0; mi < 2; mi++)
#pragma unroll
                for (int ni = 0; ni < 8; ni++) {
                    unsigned b0 = b[ni >> 1][(ni & 1) * 2];
                    unsigned b1 = b[ni >> 1][(ni & 1) * 2 + 1];
                    asm volatile(
                        "mma.sync.aligned.m16n8k16.row.col.f32.bf16.bf16.f32 "
                        "{%0,%1,%2,%3}, {%4,%5,%6,%7}, {%8,%9}, {%0,%1,%2,%3};\n"
                        : "+f"(acc[mi][ni][0]), "+f"(acc[mi][ni][1]),
                          "+f"(acc[mi][ni][2]), "+f"(acc[mi][ni][3])
                        : "r"(a[mi][0]), "r"(a[mi][1]), "r"(a[mi][2]), "r"(a[mi][3]),
                          "r"(b0), "r"(b1));
                }
        }
        __syncthreads();
    }

#pragma unroll
    for (int mi = 0; mi < 2; mi++) {
#pragma unroll
        for (int ni = 0; ni < 8; ni++) {
            int col = n0 + wn + ni * 8 + (lane & 3) * 2;
            float bx = bias[col], by = bias[col + 1];
            int row0 = m0 + wm + mi * 16 + (lane >> 2);
            float2 v0 = make_float2(acc[mi][ni][0] + bx, acc[mi][ni][1] + by);
            float2 v1 = make_float2(acc[mi][ni][2] + bx, acc[mi][ni][3] + by);
            *(float2*)(out + (size_t)row0 * G4 + col) = v0;
            *(float2*)(out + (size_t)(row0 + 8) * G4 + col) = v1;
        }
    }
}

// ------------------------- LSTM recurrence: DSMEM all-to-all, mbarrier-synced ---------
// 4 clusters x 16 CTAs. CTA rank owns 32 h-dims x 4 gates (W slice resident in SMEM,
// B fragments hoisted to registers). Per step: mbar wait (acquire.cluster) -> mma from
// double-buffered staging -> k-half reduce -> gate math (tanh.approx) -> pack h b64 via
// shfl -> st.shared::cluster to all 16 CTAs -> release arrive on all 16 mbars.
#define WPAD 136
#define SPAD 520
#define GPAD 136
#define STG_ROW   (SPAD*2)              /* 1040 B */
#define STG_PAR   (16*STG_ROW)          /* 16640 B per parity buffer */
#define OFF_STG   (512*WPAD*2)          /* 139264 */
#define OFF_GATES (OFF_STG + 2*STG_PAR) /* 172544 */
#define OFF_CSM   (OFF_GATES + 16*GPAD*4)
#define OFF_MBAR  (OFF_CSM + 512*4)
#define LSM_BYTES (OFF_MBAR + 64)

__global__ __launch_bounds__(512, 1) __cluster_dims__(16, 1, 1)
void k_lstm2(void)
{
    extern __shared__ char smraw[];
    __nv_bfloat16* Ws   = (__nv_bfloat16*)smraw;                 // [512][136]
    float* gates = (float*)(smraw + OFF_GATES);                  // [16][136]
    float* csm   = (float*)(smraw + OFF_CSM);                    // [16][32]

    int tid = threadIdx.x;
    int wid = tid >> 5;
    int lane = tid & 31;
    int cid = blockIdx.x >> 4;
    int rank = blockIdx.x & 15;
    int dir = cid >> 1;
    int bg  = cid & 1;
    int j0  = rank * 32;

    const __nv_bfloat16* Whh = g_wb2[dir];
    const float* xw = g_xw[dir];
    float* hs = g_hs[dir];

    unsigned sbase = smaddr(smraw);
    unsigned stg0  = sbase + OFF_STG;
    unsigned mbar0 = sbase + OFF_MBAR;

    if (tid == 0) {
        asm volatile("mbarrier.init.shared.b64 [%0], 16;" :: "r"(mbar0) : "memory");
        asm volatile("mbarrier.init.shared.b64 [%0], 16;" :: "r"(mbar0 + 8) : "memory");
    }
    // zero staging parity 0 (h0 = 0) and c
    for (int c = tid; c < STG_PAR / 8; c += 512)
        ((uint2*)(smraw + OFF_STG))[c] = make_uint2(0, 0);
    csm[tid] = 0.f;
    // load W slice: cols {q*512 + j0 + j : q<4, j<32} -> Ws[k][q*32+j]
    for (int c = tid; c < 512 * 16; c += 512) {
        int k = c >> 4, ch = c & 15;
        int q = ch >> 2, jb = (ch & 3) * 8;
        uint4 v = *(const uint4*)(Whh + (size_t)k * G4 + q * 512 + j0 + jb);
        *(uint4*)(Ws + k * WPAD + q * 32 + jb) = v;
    }
    __syncthreads();
    asm volatile("barrier.cluster.arrive.aligned;" ::: "memory");
    asm volatile("barrier.cluster.wait.aligned;" ::: "memory");

    int kh = wid & 1;           // k half
    int ng = wid >> 1;          // n group (16 cols)
    int kbase = kh * 256;
    int ngc = ng * 16;

    // hoist B fragments (loop-invariant): 16 k16-tiles x 4 regs
    unsigned bfr[16][4];
#pragma unroll
    for (int kk = 0; kk < 16; kk++) {
        int k0 = kbase + kk * 16;
        unsigned addr = smaddr(Ws + (k0 + (lane & 15)) * WPAD + ngc + 8 * (lane >> 4));
        asm volatile("ldmatrix.sync.aligned.m8n8.x4.trans.shared.b16 {%0,%1,%2,%3}, [%4];\n"
                     : "=r"(bfr[kk][0]), "=r"(bfr[kk][1]), "=r"(bfr[kk][2]), "=r"(bfr[kk][3])
                     : "r"(addr));
    }

    // DSMEM destinations: lane chunk = (lane>>2) (8B of row wid), targets (lane&3)+4i
    unsigned pstg[4];
#pragma unroll
    for (int i = 0; i < 4; i++) {
        unsigned tgt = (lane & 3) + 4 * i;
        unsigned r;
        asm("mapa.shared::cluster.u32 %0, %1, %2;" : "=r"(r) : "r"(stg0), "r"(tgt));
        pstg[i] = r + (unsigned)(wid * STG_ROW + j0 * 2 + (lane >> 2) * 8);
    }
    unsigned pmbar = 0;
    if (wid == 0 && lane < 16)
        asm("mapa.shared::cluster.u32 %0, %1, %2;" : "=r"(pmbar) : "r"(mbar0), "r"(lane));

    int ph0 = 0, ph1 = 0;

    for (int s = 0; s < TT; s++) {
        int p = s & 1;
        int t = dir ? (TT - 1 - s) : s;

        // xw prefetch (gb=wid, gj=lane) — independent of staging
        const float* xrow = xw + (size_t)(t * BB + bg * 16 + wid) * G4 + j0 + lane;
        float xq0 = xrow[0];
        float xq1 = xrow[512];
        float xq2 = xrow[1024];
        float xq3 = xrow[1536];

        if (s) {
            unsigned mb = mbar0 + p * 8;
            int phv = p ? ph1 : ph0;
            asm volatile(
                "{\n\t.reg .pred P;\n"
                "WL%=:\n\t"
                "mbarrier.try_wait.parity.acquire.cluster.shared::cta.b64 P, [%0], %1, 0x989680;\n\t"
                "@P bra WD%=;\n\t"
                "bra WL%=;\n"
                "WD%=:\n\t}"
                :: "r"(mb), "r"(phv) : "memory");
            if (p) ph1 ^= 1; else ph0 ^= 1;
        }

        // mma: M=16 (batches), N=16 (ng), K=256 (kh), A from staging[p]
        unsigned stgp = stg0 + (unsigned)(p * STG_PAR);
        float acc[2][4];
#pragma unroll
        for (int i = 0; i < 2; i++)
#pragma unroll
            for (int j = 0; j < 4; j++) acc[i][j] = 0.f;

#pragma unroll
        for (int kk = 0; kk < 16; kk++) {
            int k0 = kbase + kk * 16;
            unsigned a[4];
            unsigned addr = stgp + (unsigned)((lane & 15) * STG_ROW + k0 * 2 + (lane >> 4) * 16);
            asm volatile("ldmatrix.sync.aligned.m8n8.x4.shared.b16 {%0,%1,%2,%3}, [%4];\n"
                         : "=r"(a[0]), "=r"(a[1]), "=r"(a[2]), "=r"(a[3]) : "r"(addr));
#pragma unroll
            for (int nt = 0; nt < 2; nt++) {
                asm volatile(
                    "mma.sync.aligned.m16n8k16.row.col.f32.bf16.bf16.f32 "
                    "{%0,%1,%2,%3}, {%4,%5,%6,%7}, {%8,%9}, {%0,%1,%2,%3};\n"
                    : "+f"(acc[nt][0]), "+f"(acc[nt][1]), "+f"(acc[nt][2]), "+f"(acc[nt][3])
                    : "r"(a[0]), "r"(a[1]), "r"(a[2]), "r"(a[3]),
                      "r"(bfr[kk][nt * 2]), "r"(bfr[kk][nt * 2 + 1]));
            }
        }

        // reduce k-halves via SMEM
        int r = lane >> 2;
        int cbase = ngc + (lane & 3) * 2;
        if (kh) {
#pragma unroll
            for (int nt = 0; nt < 2; nt++) {
                *(float2*)(gates + r * GPAD + cbase + nt * 8)       = make_float2(acc[nt][0], acc[nt][1]);
                *(float2*)(gates + (r + 8) * GPAD + cbase + nt * 8) = make_float2(acc[nt][2], acc[nt][3]);
            }
        }
        __syncthreads();
        if (!kh) {
#pragma unroll
            for (int nt = 0; nt < 2; nt++) {
                float2* p0 = (float2*)(gates + r * GPAD + cbase + nt * 8);
                float2* p1 = (float2*)(gates + (r + 8) * GPAD + cbase + nt * 8);
                float2 v0 = *p0, v1 = *p1;
                v0.x += acc[nt][0]; v0.y += acc[nt][1];
                v1.x += acc[nt][2]; v1.y += acc[nt][3];
                *p0 = v0; *p1 = v1;
            }
        }
        __syncthreads();

        // gate math: thread -> (batch wid, dim lane); sigmoid via tanh.approx
        float h;
        {
            float gi = gates[wid * GPAD + lane]      + xq0;
            float gf = gates[wid * GPAD + 32 + lane] + xq1;
            float gg = gates[wid * GPAD + 64 + lane] + xq2;
            float go = gates[wid * GPAD + 96 + lane] + xq3;
            float c  = csm[wid * 32 + lane];
            float si = 0.5f * tanha(0.5f * gi) + 0.5f;
            float sf = 0.5f * tanha(0.5f * gf) + 0.5f;
            float so = 0.5f * tanha(0.5f * go) + 0.5f;
            c = sf * c + si * tanha(gg);
            csm[wid * 32 + lane] = c;
            h = so * tanha(c);
            hs[((size_t)t * BB + bg * 16 + wid) * HH + j0 + lane] = h;
        }

        if (s + 1 < TT) {
            // pack 4 h values (dims 4*(lane>>2)..+3) into b64 via shfl.bfly
            __nv_bfloat16 hb16 = __float2bfloat16(h);
            unsigned hb = (unsigned)(*(unsigned short*)&hb16);
            unsigned o1 = __shfl_xor_sync(0xffffffffu, hb, 1);
            unsigned p32 = (lane & 1) ? ((hb << 16) | o1) : ((o1 << 16) | hb);
            unsigned o2 = __shfl_xor_sync(0xffffffffu, p32, 2);
            unsigned lo = (lane & 2) ? o2 : p32;
            unsigned hi = (lane & 2) ? p32 : o2;
            unsigned long long v64 = ((unsigned long long)hi << 32) | (unsigned long long)lo;
            unsigned off = (unsigned)((p ^ 1) * STG_PAR);
#pragma unroll
            for (int i = 0; i < 4; i++)
                asm volatile("st.shared::cluster.b64 [%0], %1;" :: "r"(pstg[i] + off), "l"(v64) : "memory");
            __syncthreads();
            if (wid == 0 && lane < 16)
                asm volatile("mbarrier.arrive.release.cluster.shared::cluster.b64 _, [%0];"
                             :: "r"(pmbar + (unsigned)((p ^ 1) * 8)) : "memory");
        }
    }

    asm volatile("barrier.cluster.arrive.aligned;" ::: "memory");
    asm volatile("barrier.cluster.wait.aligned;" ::: "memory");
}

// ------------------------- tag projection -------------------------
__global__ __launch_bounds__(256) void k_tag(const float* __restrict__ Wtag,
                                             const float* __restrict__ btag)
{
    extern __shared__ float sm[];
    float* Wt = sm;                 // [30][1024] (transposed)
    float* hh = Wt + KK * 1024;     // [1024]
    int tid = threadIdx.x;
    for (int idx = tid; idx < 1024 * KK; idx += 256) {
        int d = idx / KK;
        int k = idx - d * KK;
        Wt[k * 1024 + d] = Wtag[idx];
    }
    __syncthreads();
    int w = tid >> 5, lane = tid & 31;
    for (int m = blockIdx.x; m < MTOT; m += gridDim.x) {
        int t = m >> 5, b = m & 31;
        {
            int hidx = tid;
            const float* src = (hidx < 128)
                ? (g_hs[0] + ((size_t)t * BB + b) * HH + hidx * 4)
                : (g_hs[1] + ((size_t)t * BB + b) * HH + (hidx - 128) * 4);
            *(float4*)(&hh[hidx * 4]) = *(const float4*)src;
        }
        __syncthreads();
#pragma unroll
        for (int q = 0; q < 4; q++) {
            int k = w + q * 8;
            if (k < KK) {
                const float* wr = Wt + k * 1024;
                float s = 0.f;
#pragma unroll
                for (int i = 0; i < 8; i++) {
                    int d = lane * 4 + i * 128;
                    float4 hv = *(const float4*)(&hh[d]);
                    float4 wv = *(const float4*)(&wr[d]);
                    s += hv.x * wv.x + hv.y * wv.y + hv.z * wv.z + hv.w * wv.w;
                }
#pragma unroll
                for (int off = 16; off; off >>= 1)
                    s += __shfl_down_sync(0xffffffffu, s, off);
                if (lane == 0)
                    g_feats[((size_t)b * TT + t) * KK + k] = s + btag[k];
            }
        }
        __syncthreads();
    }
}

// ------------------------- CRF NLL (one warp per sentence) -------------------------
__global__ void k_crf(const float* __restrict__ trans, const int* __restrict__ tags,
                      float* __restrict__ out)
{
    int b = blockIdx.x;
    int lane = threadIdx.x;
    float trow[KK];
    int lr = (lane < KK) ? lane : 0;
#pragma unroll
    for (int p = 0; p < KK; p++) trow[p] = trans[lr * KK + p];
    float alpha = (lane == TSTART) ? 0.f : NEGV;
    const float* fb = g_feats + (size_t)b * TT * KK;
    for (int t = 0; t < TT; t++) {
        float emit = (lane < KK) ? fb[t * KK + lane] : 0.f;
        float v[KK];
        float vmax = -1e30f;
#pragma unroll
        for (int p = 0; p < KK; p++) {
            v[p] = __shfl_sync(0xffffffffu, alpha, p) + trow[p];
            vmax = fmaxf(vmax, v[p]);
        }
        float ssum = 0.f;
#pragma unroll
        for (int p = 0; p < KK; p++) ssum += __expf(v[p] - vmax);
        float na = vmax + __logf(ssum) + emit;
        alpha = (lane < KK) ? na : NEGV;
    }
    float v = (lane < KK) ? (alpha + trans[TSTOP * KK + lane]) : -1e30f;
    float m = v;
#pragma unroll
    for (int off = 16; off; off >>= 1) m = fmaxf(m, __shfl_xor_sync(0xffffffffu, m, off));
    float e = (lane < KK) ? __expf(v - m) : 0.f;
#pragma unroll
    for (int off = 16; off; off >>= 1) e += __shfl_xor_sync(0xffffffffu, e, off);
    float logz = m + __logf(e);
    const int* tg = tags + b * TT;
    float gold = 0.f;
    for (int j = lane; j < TT + 1; j += 32) {
        int prev = (j == 0) ? TSTART : tg[j - 1];
        int nxt  = (j < TT) ? tg[j] : TSTOP;
        gold += trans[nxt * KK + prev];
        if (j < TT) gold += fb[j * KK + tg[j]];
    }
#pragma unroll
    for (int off = 16; off; off >>= 1) gold += __shfl_xor_sync(0xffffffffu, gold, off);
    if (lane == 0) out[b] = logz - gold;
}

// ------------------------- launcher -------------------------
extern "C" void kernel_launch(void* const* d_in, const int* in_sizes, int n_in,
                              void* d_out, int out_size)
{
    const int*   ids   = (const int*)  d_in[0];
    const int*   tags  = (const int*)  d_in[1];
    const float* embed = (const float*)d_in[2];
    const float* Wihf  = (const float*)d_in[3];
    const float* Whhf  = (const float*)d_in[4];
    const float* bf    = (const float*)d_in[5];
    const float* Wihb  = (const float*)d_in[6];
    const float* Whhb  = (const float*)d_in[7];
    const float* bb    = (const float*)d_in[8];
    const float* Wtag  = (const float*)d_in[9];
    const float* btag  = (const float*)d_in[10];
    const float* trans = (const float*)d_in[11];
    float* out = (float*)d_out;

    size_t tsm = (size_t)(KK * 1024 + 1024) * sizeof(float);
    cudaFuncSetAttribute(k_tag, cudaFuncAttributeMaxDynamicSharedMemorySize, (int)tsm);
    cudaFuncSetAttribute(k_lstm2, cudaFuncAttributeMaxDynamicSharedMemorySize, LSM_BYTES);
    cudaFuncSetAttribute(k_lstm2, cudaFuncAttributeNonPortableClusterSizeAllowed, 1);

    {
        size_t nx = (size_t)MTOT * (DIN / 4);
        k_castx<<<(unsigned)((nx + 255) / 256), 256>>>(embed, ids);              // 0
        size_t nwt = 2 * NW4 + 2 * NH4;
        k_castw<<<(unsigned)((nwt + 255) / 256), 256>>>(Wihf, Wihb, Whhf, Whhb); // 1
    }
    dim3 gg(G4 / BN, MTOT / BM);
    k_gemm<<<gg, 256>>>(bf, 0);                                                  // 2
    k_gemm<<<gg, 256>>>(bb, 1);                                                  // 3
    k_zero<<<32, 256>>>();                                                       // 4
    k_lstm2<<<64, 512, LSM_BYTES>>>();                                           // 5  <- ncu
    k_tag<<<148, 256, tsm>>>(Wtag, btag);                                        // 6
    k_crf<<<BB, 32>>>(trans, tags, out);                                         // 7
}

// round 6
// speedup vs baseline: 4.9886x; 1.0628x over previous
#include <cuda_runtime.h>
#include <cuda_bf16.h>
#include <math.h>

#define BB 32
#define TT 512
#define DIN 1824
#define HH 512
#define G4 2048
#define KK 30
#define TSTART 28
#define TSTOP 29
#define NEGV (-10000.0f)
#define MTOT (TT*BB)            /* 16384 */

// ------------------------- device scratch -------------------------
__device__ __nv_bfloat16 g_xwb[2][(size_t)MTOT*G4];  // input proj, bf16
__device__ __nv_bfloat16 g_hsb[(size_t)MTOT*2*HH];   // [m][hf(512)|hb(512)] bf16, m=t*B+b
__device__ float g_feats[(size_t)BB*TT*KK];          // [b][t][k]
__device__ __nv_bfloat16 g_xb[(size_t)MTOT*DIN];     // gathered embeddings, bf16
__device__ __nv_bfloat16 g_wb[2][(size_t)DIN*G4];    // W_ih f/b, bf16
__device__ __nv_bfloat16 g_wb2[2][(size_t)HH*G4];    // W_hh f/b, bf16

__device__ __forceinline__ unsigned smaddr(const void* p)
{
    return (unsigned)__cvta_generic_to_shared(p);
}

__device__ __forceinline__ float tanha(float x)
{
    float r;
    asm("tanh.approx.f32 %0, %1;" : "=f"(r) : "f"(x));
    return r;
}

// ------------------------- cast kernels -------------------------
__global__ __launch_bounds__(256) void k_castx(const float* __restrict__ embed,
                                               const int* __restrict__ ids)
{
    size_t idx = (size_t)blockIdx.x * 256 + threadIdx.x;
    if (idx >= (size_t)MTOT * (DIN / 4)) return;
    int m = (int)(idx / (DIN / 4));
    int q = (int)(idx % (DIN / 4));
    int id = ids[(m & 31) * TT + (m >> 5)];
    float4 v = *(const float4*)(embed + (size_t)id * DIN + 4 * q);
    __nv_bfloat162 lo = __floats2bfloat162_rn(v.x, v.y);
    __nv_bfloat162 hi = __floats2bfloat162_rn(v.z, v.w);
    uint2 pk; pk.x = *(unsigned*)&lo; pk.y = *(unsigned*)&hi;
    *(uint2*)(g_xb + (size_t)m * DIN + 4 * q) = pk;
}

#define NW4 ((size_t)DIN*G4/4)
#define NH4 ((size_t)HH*G4/4)

__global__ __launch_bounds__(256) void k_castw(const float* __restrict__ f0,
                                               const float* __restrict__ f1,
                                               const float* __restrict__ f2,
                                               const float* __restrict__ f3)
{
    size_t idx = (size_t)blockIdx.x * 256 + threadIdx.x;
    const float* src; __nv_bfloat16* dst;
    if (idx < NW4)                    { src = f0; dst = g_wb[0]; }
    else if (idx < 2 * NW4)           { src = f1; dst = g_wb[1]; idx -= NW4; }
    else if (idx < 2 * NW4 + NH4)     { src = f2; dst = g_wb2[0]; idx -= 2 * NW4; }
    else if (idx < 2 * NW4 + 2 * NH4) { src = f3; dst = g_wb2[1]; idx -= 2 * NW4 + NH4; }
    else return;
    float4 v = *(const float4*)(src + 4 * idx);
    __nv_bfloat162 lo = __floats2bfloat162_rn(v.x, v.y);
    __nv_bfloat162 hi = __floats2bfloat162_rn(v.z, v.w);
    uint2 pk; pk.x = *(unsigned*)&lo; pk.y = *(unsigned*)&hi;
    *(uint2*)(dst + 4 * idx) = pk;
}

// ------------------------- input GEMM: both dirs, 3-stage cp.async, bf16 out ----------
#define BM 128
#define BN 128
#define BK 32
#define APAD 8
#define BPAD 8
#define NKT (DIN / BK)   /* 57 */
#define GA_STRIDE (BK + APAD)            /* 40 */
#define GB_STRIDE (BN + BPAD)            /* 136 */
#define GA_BUF (BM * GA_STRIDE)          /* 5120 elems */
#define GB_BUF (BK * GB_STRIDE)          /* 4352 elems */
#define GSMEM ((3 * (GA_BUF + GB_BUF)) * 2)

__global__ __launch_bounds__(256) void k_gemm(const float* __restrict__ bf_,
                                              const float* __restrict__ bb_)
{
    extern __shared__ char gsm[];
    __nv_bfloat16* As = (__nv_bfloat16*)gsm;          // [3][128][40]
    __nv_bfloat16* Bs = As + 3 * GA_BUF;              // [3][32][136]

    int dir = blockIdx.x >> 4;
    int n0 = (blockIdx.x & 15) * BN;
    const float* bias = dir ? bb_ : bf_;
    const __nv_bfloat16* A = g_xb;
    const __nv_bfloat16* Bw = g_wb[dir];
    __nv_bfloat16* out = g_xwb[dir];

    int tid = threadIdx.x;
    int wid = tid >> 5;
    int lane = tid & 31;
    int m0 = blockIdx.y * BM;
    int wm = (wid & 3) * 32;
    int wn = (wid >> 2) * 64;

    float acc[2][8][4];
#pragma unroll
    for (int i = 0; i < 2; i++)
#pragma unroll
        for (int j = 0; j < 8; j++)
#pragma unroll
            for (int r = 0; r < 4; r++) acc[i][j][r] = 0.f;

    auto loadAB = [&](int buf, int k0) {
        __nv_bfloat16* Ab = As + buf * GA_BUF;
        __nv_bfloat16* Bb = Bs + buf * GB_BUF;
#pragma unroll
        for (int j = 0; j < 2; j++) {
            int c = tid + j * 256;
            int r = c >> 2, q = c & 3;
            unsigned dst = smaddr(Ab + r * GA_STRIDE + q * 8);
            const __nv_bfloat16* src = A + (size_t)(m0 + r) * DIN + k0 + q * 8;
            asm volatile("cp.async.cg.shared.global [%0], [%1], 16;\n" :: "r"(dst), "l"(src));
        }
#pragma unroll
        for (int j = 0; j < 2; j++) {
            int c = tid + j * 256;
            int r = c >> 4, q = c & 15;
            unsigned dst = smaddr(Bb + r * GB_STRIDE + q * 8);
            const __nv_bfloat16* src = Bw + (size_t)(k0 + r) * G4 + n0 + q * 8;
            asm volatile("cp.async.cg.shared.global [%0], [%1], 16;\n" :: "r"(dst), "l"(src));
        }
    };

    loadAB(0, 0);
    asm volatile("cp.async.commit_group;\n");
    loadAB(1, BK);
    asm volatile("cp.async.commit_group;\n");

    int buf = 0;
    for (int kt = 0; kt < NKT; kt++) {
        asm volatile("cp.async.wait_group 1;\n");
        __syncthreads();
        if (kt + 2 < NKT) {
            int nb = buf + 2; if (nb >= 3) nb -= 3;
            loadAB(nb, (kt + 2) * BK);
        }
        asm volatile("cp.async.commit_group;\n");

        __nv_bfloat16* Ab = As + buf * GA_BUF;
        __nv_bfloat16* Bb = Bs + buf * GB_BUF;
#pragma unroll
        for (int ks = 0; ks < 2; ks++) {
            int k0 = ks * 16;
            unsigned a[2][4];
#pragma unroll
            for (int mi = 0; mi < 2; mi++) {
                unsigned addr = smaddr(Ab + (wm + mi * 16 + (lane & 15)) * GA_STRIDE + k0 + 8 * (lane >> 4));
                asm volatile("ldmatrix.sync.aligned.m8n8.x4.shared.b16 {%0,%1,%2,%3}, [%4];\n"
                             : "=r"(a[mi][0]), "=r"(a[mi][1]), "=r"(a[mi][2]), "=r"(a[mi][3])
                             : "r"(addr));
            }
            unsigned b[4][4];
#pragma unroll
            for (int nj = 0; nj < 4; nj++) {
                unsigned addr = smaddr(Bb + (k0 + (lane & 15)) * GB_STRIDE + wn + nj * 16 + 8 * (lane >> 4));
                asm volatile("ldmatrix.sync.aligned.m8n8.x4.trans.shared.b16 {%0,%1,%2,%3}, [%4];\n"
                             : "=r"(b[nj][0]), "=r"(b[nj][1]), "=r"(b[nj][2]), "=r"(b[nj][3])
                             : "r"(addr));
            }
#pragma unroll
            for (int mi = 0; mi < 2; mi++)
#pragma unroll
                for (int ni = 0; ni < 8; ni++) {
                    unsigned b0 = b[ni >> 1][(ni & 1) * 2];
                    unsigned b1 = b[ni >> 1][(ni & 1) * 2 + 1];
                    asm volatile(
                        "mma.sync.aligned.m16n8k16.row.col.f32.bf16.bf16.f32 "
                        "{%0,%1,%2,%3}, {%4,%5,%6,%7}, {%8,%9}, {%0,%1,%2,%3};\n"
                        : "+f"(acc[mi][ni][0]), "+f"(acc[mi][ni][1]),
                          "+f"(acc[mi][ni][2]), "+f"(acc[mi][ni][3])
                        : "r"(a[mi][0]), "r"(a[mi][1]), "r"(a[mi][2]), "r"(a[mi][3]),
                          "r"(b0), "r"(b1));
                }
        }
        __syncthreads();
        if (++buf == 3) buf = 0;
    }

#pragma unroll
    for (int mi = 0; mi < 2; mi++) {
#pragma unroll
        for (int ni = 0; ni < 8; ni++) {
            int col = n0 + wn + ni * 8 + (lane & 3) * 2;
            float bx = bias[col], by = bias[col + 1];
            int row0 = m0 + wm + mi * 16 + (lane >> 2);
            __nv_bfloat162 v0 = __floats2bfloat162_rn(acc[mi][ni][0] + bx, acc[mi][ni][1] + by);
            __nv_bfloat162 v1 = __floats2bfloat162_rn(acc[mi][ni][2] + bx, acc[mi][ni][3] + by);
            *(__nv_bfloat162*)(out + (size_t)row0 * G4 + col) = v0;
            *(__nv_bfloat162*)(out + (size_t)(row0 + 8) * G4 + col) = v1;
        }
    }
}

// ------------------------- LSTM recurrence: DSMEM all-to-all, mbarrier-synced ---------
#define WPAD 136
#define SPAD 520
#define GPAD 136
#define STG_ROW   (SPAD*2)              /* 1040 B */
#define STG_PAR   (16*STG_ROW)          /* 16640 B per parity buffer */
#define OFF_STG   (512*WPAD*2)          /* 139264 */
#define OFF_GATES (OFF_STG + 2*STG_PAR)
#define OFF_CSM   (OFF_GATES + 16*GPAD*4)
#define OFF_MBAR  (OFF_CSM + 512*4)
#define LSM_BYTES (OFF_MBAR + 64)

__global__ __launch_bounds__(512, 1) __cluster_dims__(16, 1, 1)
void k_lstm2(void)
{
    extern __shared__ char smraw[];
    __nv_bfloat16* Ws   = (__nv_bfloat16*)smraw;                 // [512][136]
    float* gates = (float*)(smraw + OFF_GATES);                  // [16][136]
    float* csm   = (float*)(smraw + OFF_CSM);                    // [16][32]

    int tid = threadIdx.x;
    int wid = tid >> 5;
    int lane = tid & 31;
    int cid = blockIdx.x >> 4;
    int rank = blockIdx.x & 15;
    int dir = cid >> 1;
    int bg  = cid & 1;
    int j0  = rank * 32;

    const __nv_bfloat16* Whh = g_wb2[dir];
    const __nv_bfloat16* xw = g_xwb[dir];

    unsigned sbase = smaddr(smraw);
    unsigned stg0  = sbase + OFF_STG;
    unsigned mbar0 = sbase + OFF_MBAR;

    if (tid == 0) {
        asm volatile("mbarrier.init.shared.b64 [%0], 16;" :: "r"(mbar0) : "memory");
        asm volatile("mbarrier.init.shared.b64 [%0], 16;" :: "r"(mbar0 + 8) : "memory");
    }
    for (int c = tid; c < STG_PAR / 8; c += 512)
        ((uint2*)(smraw + OFF_STG))[c] = make_uint2(0, 0);
    csm[tid] = 0.f;
    for (int c = tid; c < 512 * 16; c += 512) {
        int k = c >> 4, ch = c & 15;
        int q = ch >> 2, jb = (ch & 3) * 8;
        uint4 v = *(const uint4*)(Whh + (size_t)k * G4 + q * 512 + j0 + jb);
        *(uint4*)(Ws + k * WPAD + q * 32 + jb) = v;
    }
    __syncthreads();
    asm volatile("barrier.cluster.arrive.aligned;" ::: "memory");
    asm volatile("barrier.cluster.wait.aligned;" ::: "memory");

    int kh = wid & 1;
    int ng = wid >> 1;
    int kbase = kh * 256;
    int ngc = ng * 16;

    unsigned bfr[16][4];
#pragma unroll
    for (int kk = 0; kk < 16; kk++) {
        int k0 = kbase + kk * 16;
        unsigned addr = smaddr(Ws + (k0 + (lane & 15)) * WPAD + ngc + 8 * (lane >> 4));
        asm volatile("ldmatrix.sync.aligned.m8n8.x4.trans.shared.b16 {%0,%1,%2,%3}, [%4];\n"
                     : "=r"(bfr[kk][0]), "=r"(bfr[kk][1]), "=r"(bfr[kk][2]), "=r"(bfr[kk][3])
                     : "r"(addr));
    }

    // DSMEM destinations: 16B chunk q = lane>>3, targets (lane&7) and (lane&7)+8
    unsigned pst[2];
#pragma unroll
    for (int i = 0; i < 2; i++) {
        unsigned tgt = (lane & 7) + 8 * i;
        unsigned r;
        asm("mapa.shared::cluster.u32 %0, %1, %2;" : "=r"(r) : "r"(stg0), "r"(tgt));
        pst[i] = r + (unsigned)(wid * STG_ROW + j0 * 2 + (lane >> 3) * 16);
    }
    unsigned pmbar = 0;
    if (wid == 0 && lane < 16)
        asm("mapa.shared::cluster.u32 %0, %1, %2;" : "=r"(pmbar) : "r"(mbar0), "r"(lane));

    int ph0 = 0, ph1 = 0;

    for (int s = 0; s < TT; s++) {
        int p = s & 1;
        int t = dir ? (TT - 1 - s) : s;

        const __nv_bfloat16* xrow = xw + (size_t)(t * BB + bg * 16 + wid) * G4 + j0 + lane;
        float xq0 = __bfloat162float(xrow[0]);
        float xq1 = __bfloat162float(xrow[512]);
        float xq2 = __bfloat162float(xrow[1024]);
        float xq3 = __bfloat162float(xrow[1536]);

        if (s) {
            unsigned mb = mbar0 + p * 8;
            int phv = p ? ph1 : ph0;
            asm volatile(
                "{\n\t.reg .pred P;\n"
                "WL%=:\n\t"
                "mbarrier.try_wait.parity.acquire.cluster.shared::cta.b64 P, [%0], %1, 0x989680;\n\t"
                "@P bra WD%=;\n\t"
                "bra WL%=;\n"
                "WD%=:\n\t}"
                :: "r"(mb), "r"(phv) : "memory");
            if (p) ph1 ^= 1; else ph0 ^= 1;
        }

        unsigned stgp = stg0 + (unsigned)(p * STG_PAR);
        float acc[2][4];
#pragma unroll
        for (int i = 0; i < 2; i++)
#pragma unroll
            for (int j = 0; j < 4; j++) acc[i][j] = 0.f;

#pragma unroll
        for (int kk = 0; kk < 16; kk++) {
            int k0 = kbase + kk * 16;
            unsigned a[4];
            unsigned addr = stgp + (unsigned)((lane & 15) * STG_ROW + k0 * 2 + (lane >> 4) * 16);
            asm volatile("ldmatrix.sync.aligned.m8n8.x4.shared.b16 {%0,%1,%2,%3}, [%4];\n"
                         : "=r"(a[0]), "=r"(a[1]), "=r"(a[2]), "=r"(a[3]) : "r"(addr));
#pragma unroll
            for (int nt = 0; nt < 2; nt++) {
                asm volatile(
                    "mma.sync.aligned.m16n8k16.row.col.f32.bf16.bf16.f32 "
                    "{%0,%1,%2,%3}, {%4,%5,%6,%7}, {%8,%9}, {%0,%1,%2,%3};\n"
                    : "+f"(acc[nt][0]), "+f"(acc[nt][1]), "+f"(acc[nt][2]), "+f"(acc[nt][3])
                    : "r"(a[0]), "r"(a[1]), "r"(a[2]), "r"(a[3]),
                      "r"(bfr[kk][nt * 2]), "r"(bfr[kk][nt * 2 + 1]));
            }
        }

        int r = lane >> 2;
        int cbase = ngc + (lane & 3) * 2;
        if (kh) {
#pragma unroll
            for (int nt = 0; nt < 2; nt++) {
                *(float2*)(gates + r * GPAD + cbase + nt * 8)       = make_float2(acc[nt][0], acc[nt][1]);
                *(float2*)(gates + (r + 8) * GPAD + cbase + nt * 8) = make_float2(acc[nt][2], acc[nt][3]);
            }
        }
        __syncthreads();
        if (!kh) {
#pragma unroll
            for (int nt = 0; nt < 2; nt++) {
                float2* p0 = (float2*)(gates + r * GPAD + cbase + nt * 8);
                float2* p1 = (float2*)(gates + (r + 8) * GPAD + cbase + nt * 8);
                float2 v0 = *p0, v1 = *p1;
                v0.x += acc[nt][0]; v0.y += acc[nt][1];
                v1.x += acc[nt][2]; v1.y += acc[nt][3];
                *p0 = v0; *p1 = v1;
            }
        }
        __syncthreads();

        float h;
        {
            float gi = gates[wid * GPAD + lane]      + xq0;
            float gf = gates[wid * GPAD + 32 + lane] + xq1;
            float gg = gates[wid * GPAD + 64 + lane] + xq2;
            float go = gates[wid * GPAD + 96 + lane] + xq3;
            float c  = csm[wid * 32 + lane];
            float si = 0.5f * tanha(0.5f * gi) + 0.5f;
            float sf = 0.5f * tanha(0.5f * gf) + 0.5f;
            float so = 0.5f * tanha(0.5f * go) + 0.5f;
            c = sf * c + si * tanha(gg);
            csm[wid * 32 + lane] = c;
            h = so * tanha(c);
        }
        __nv_bfloat16 hb16 = __float2bfloat16(h);
        g_hsb[(size_t)(t * BB + bg * 16 + wid) * (2 * HH) + dir * HH + j0 + lane] = hb16;

        if (s + 1 < TT) {
            // pack 8 h values into 16B via 3x shfl.bfly
            unsigned hb = (unsigned)(*(unsigned short*)&hb16);
            unsigned o1 = __shfl_xor_sync(0xffffffffu, hb, 1);
            unsigned p32 = (lane & 1) ? ((hb << 16) | o1) : ((o1 << 16) | hb);
            unsigned o2 = __shfl_xor_sync(0xffffffffu, p32, 2);
            unsigned lo = (lane & 2) ? o2 : p32;
            unsigned hi = (lane & 2) ? p32 : o2;
            unsigned lo2 = __shfl_xor_sync(0xffffffffu, lo, 4);
            unsigned hi2 = __shfl_xor_sync(0xffffffffu, hi, 4);
            unsigned r0 = (lane & 4) ? lo2 : lo;
            unsigned r1 = (lane & 4) ? hi2 : hi;
            unsigned r2 = (lane & 4) ? lo : lo2;
            unsigned r3 = (lane & 4) ? hi : hi2;
            unsigned off = (unsigned)((p ^ 1) * STG_PAR);
#pragma unroll
            for (int i = 0; i < 2; i++)
                asm volatile("st.shared::cluster.v4.b32 [%0], {%1,%2,%3,%4};"
                             :: "r"(pst[i] + off), "r"(r0), "r"(r1), "r"(r2), "r"(r3) : "memory");
            __syncthreads();
            if (wid == 0 && lane < 16)
                asm volatile("mbarrier.arrive.release.cluster.shared::cluster.b64 _, [%0];"
                             :: "r"(pmbar + (unsigned)((p ^ 1) * 8)) : "memory");
        }
    }

    asm volatile("barrier.cluster.arrive.aligned;" ::: "memory");
    asm volatile("barrier.cluster.wait.aligned;" ::: "memory");
}

// ------------------------- tag projection: bf16 mma GEMM -------------------------
// C[16384, 30] = Hsb[16384, 1024] @ Wtag[1024, 30] (+btag), scattered to feats[b][t][k]
#define TBK 64
#define TB_STRIDE 40                    /* Bt row stride (32 cols + pad) */
#define TA_STRIDE 72                    /* As row stride (64 + 8) */
#define TA_BUF (128 * TA_STRIDE)
#define TSMEM ((1024 * TB_STRIDE + 2 * TA_BUF) * 2)

__global__ __launch_bounds__(256) void k_tag(const float* __restrict__ Wtag,
                                             const float* __restrict__ btag)
{
    extern __shared__ char tsm[];
    __nv_bfloat16* Bt = (__nv_bfloat16*)tsm;          // [1024][40]
    __nv_bfloat16* As = Bt + 1024 * TB_STRIDE;        // [2][128][72]

    int tid = threadIdx.x;
    int wid = tid >> 5;
    int lane = tid & 31;
    int m0 = blockIdx.x * 128;

    // stage B (pad cols 30/31 with zero)
    for (int idx = tid; idx < 1024 * 32; idx += 256) {
        int k = idx >> 5, n = idx & 31;
        float v = (n < KK) ? Wtag[k * KK + n] : 0.f;
        Bt[k * TB_STRIDE + n] = __float2bfloat16(v);
    }

    auto loadA = [&](int buf, int k0) {
        __nv_bfloat16* Ab = As + buf * TA_BUF;
#pragma unroll
        for (int j = 0; j < 4; j++) {
            int c = tid + j * 256;
            int r = c >> 3, q = c & 7;
            unsigned dst = smaddr(Ab + r * TA_STRIDE + q * 8);
            const __nv_bfloat16* src = g_hsb + (size_t)(m0 + r) * 1024 + k0 + q * 8;
            asm volatile("cp.async.cg.shared.global [%0], [%1], 16;\n" :: "r"(dst), "l"(src));
        }
    };

    loadA(0, 0);
    asm volatile("cp.async.commit_group;\n");
    __syncthreads();    // B ready

    float acc[4][4];
#pragma unroll
    for (int i = 0; i < 4; i++)
#pragma unroll
        for (int j = 0; j < 4; j++) acc[i][j] = 0.f;

    for (int kt = 0; kt < 1024 / TBK; kt++) {
        int buf = kt & 1;
        if (kt + 1 < 1024 / TBK) {
            loadA(buf ^ 1, (kt + 1) * TBK);
            asm volatile("cp.async.commit_group;\n");
            asm volatile("cp.async.wait_group 1;\n");
        } else {
            asm volatile("cp.async.wait_group 0;\n");
        }
        __syncthreads();
        __nv_bfloat16* Ab = As + buf * TA_BUF;
#pragma unroll
        for (int ks = 0; ks < 4; ks++) {
            int k0 = ks * 16;
            int kabs = kt * TBK + k0;
            unsigned a[4];
            unsigned addr = smaddr(Ab + (wid * 16 + (lane & 15)) * TA_STRIDE + k0 + 8 * (lane >> 4));
            asm volatile("ldmatrix.sync.aligned.m8n8.x4.shared.b16 {%0,%1,%2,%3}, [%4];\n"
                         : "=r"(a[0]), "=r"(a[1]), "=r"(a[2]), "=r"(a[3]) : "r"(addr));
            unsigned b[2][4];
#pragma unroll
            for (int nj = 0; nj < 2; nj++) {
                unsigned baddr = smaddr(Bt + (kabs + (lane & 15)) * TB_STRIDE + nj * 16 + 8 * (lane >> 4));
                asm volatile("ldmatrix.sync.aligned.m8n8.x4.trans.shared.b16 {%0,%1,%2,%3}, [%4];\n"
                             : "=r"(b[nj][0]), "=r"(b[nj][1]), "=r"(b[nj][2]), "=r"(b[nj][3])
                             : "r"(baddr));
            }
#pragma unroll
            for (int ni = 0; ni < 4; ni++) {
                unsigned b0 = b[ni >> 1][(ni & 1) * 2];
                unsigned b1 = b[ni >> 1][(ni & 1) * 2 + 1];
                asm volatile(
                    "mma.sync.aligned.m16n8k16.row.col.f32.bf16.bf16.f32 "
                    "{%0,%1,%2,%3}, {%4,%5,%6,%7}, {%8,%9}, {%0,%1,%2,%3};\n"
                    : "+f"(acc[ni][0]), "+f"(acc[ni][1]), "+f"(acc[ni][2]), "+f"(acc[ni][3])
                    : "r"(a[0]), "r"(a[1]), "r"(a[2]), "r"(a[3]), "r"(b0), "r"(b1));
            }
        }
        __syncthreads();
    }

    // scatter epilogue
#pragma unroll
    for (int ni = 0; ni < 4; ni++) {
        int col = ni * 8 + (lane & 3) * 2;
#pragma unroll
        for (int half = 0; half < 2; half++) {
            int m = m0 + wid * 16 + (lane >> 2) + half * 8;
            int b = m & 31, t = m >> 5;
            float* fo = g_feats + ((size_t)b * TT + t) * KK;
            if (col < KK)     fo[col]     = acc[ni][half * 2]     + btag[col];
            if (col + 1 < KK) fo[col + 1] = acc[ni][half * 2 + 1] + btag[col + 1];
        }
    }
}

// ------------------------- CRF NLL (one warp per sentence) -------------------------
__global__ void k_crf(const float* __restrict__ trans, const int* __restrict__ tags,
                      float* __restrict__ out)
{
    int b = blockIdx.x;
    int lane = threadIdx.x;
    float trow[KK];
    int lr = (lane < KK) ? lane : 0;
#pragma unroll
    for (int p = 0; p < KK; p++) trow[p] = trans[lr * KK + p];
    float alpha = (lane == TSTART) ? 0.f : NEGV;
    const float* fb = g_feats + (size_t)b * TT * KK;
    for (int t = 0; t < TT; t++) {
        float emit = (lane < KK) ? fb[t * KK + lane] : 0.f;
        float v[KK];
        float vmax = -1e30f;
#pragma unroll
        for (int p = 0; p < KK; p++) {
            v[p] = __shfl_sync(0xffffffffu, alpha, p) + trow[p];
            vmax = fmaxf(vmax, v[p]);
        }
        float ssum = 0.f;
#pragma unroll
        for (int p = 0; p < KK; p++) ssum += __expf(v[p] - vmax);
        float na = vmax + __logf(ssum) + emit;
        alpha = (lane < KK) ? na : NEGV;
    }
    float v = (lane < KK) ? (alpha + trans[TSTOP * KK + lane]) : -1e30f;
    float m = v;
#pragma unroll
    for (int off = 16; off; off >>= 1) m = fmaxf(m, __shfl_xor_sync(0xffffffffu, m, off));
    float e = (lane < KK) ? __expf(v - m) : 0.f;
#pragma unroll
    for (int off = 16; off; off >>= 1) e += __shfl_xor_sync(0xffffffffu, e, off);
    float logz = m + __logf(e);
    const int* tg = tags + b * TT;
    float gold = 0.f;
    for (int j = lane; j < TT + 1; j += 32) {
        int prev = (j == 0) ? TSTART : tg[j - 1];
        int nxt  = (j < TT) ? tg[j] : TSTOP;
        gold += trans[nxt * KK + prev];
        if (j < TT) gold += fb[j * KK + tg[j]];
    }
#pragma unroll
    for (int off = 16; off; off >>= 1) gold += __shfl_xor_sync(0xffffffffu, gold, off);
    if (lane == 0) out[b] = logz - gold;
}

// ------------------------- launcher -------------------------
extern "C" void kernel_launch(void* const* d_in, const int* in_sizes, int n_in,
                              void* d_out, int out_size)
{
    const int*   ids   = (const int*)  d_in[0];
    const int*   tags  = (const int*)  d_in[1];
    const float* embed = (const float*)d_in[2];
    const float* Wihf  = (const float*)d_in[3];
    const float* Whhf  = (const float*)d_in[4];
    const float* bf    = (const float*)d_in[5];
    const float* Wihb  = (const float*)d_in[6];
    const float* Whhb  = (const float*)d_in[7];
    const float* bb    = (const float*)d_in[8];
    const float* Wtag  = (const float*)d_in[9];
    const float* btag  = (const float*)d_in[10];
    const float* trans = (const float*)d_in[11];
    float* out = (float*)d_out;

    cudaFuncSetAttribute(k_gemm, cudaFuncAttributeMaxDynamicSharedMemorySize, GSMEM);
    cudaFuncSetAttribute(k_tag,  cudaFuncAttributeMaxDynamicSharedMemorySize, TSMEM);
    cudaFuncSetAttribute(k_lstm2, cudaFuncAttributeMaxDynamicSharedMemorySize, LSM_BYTES);
    cudaFuncSetAttribute(k_lstm2, cudaFuncAttributeNonPortableClusterSizeAllowed, 1);

    {
        size_t nx = (size_t)MTOT * (DIN / 4);
        k_castx<<<(unsigned)((nx + 255) / 256), 256>>>(embed, ids);              // 0
        size_t nwt = 2 * NW4 + 2 * NH4;
        k_castw<<<(unsigned)((nwt + 255) / 256), 256>>>(Wihf, Wihb, Whhf, Whhb); // 1
    }
    k_gemm<<<dim3(32, MTOT / BM), 256, GSMEM>>>(bf, bb);                         // 2
    k_lstm2<<<64, 512, LSM_BYTES>>>();                                           // 3
    k_tag<<<MTOT / 128, 256, TSMEM>>>(Wtag, btag);                               // 4
    k_crf<<<BB, 32>>>(trans, tags, out);                                         // 5
}